// round 15
// baseline (speedup 1.0000x reference)
#include <cuda_runtime.h>
#include <cuda_fp16.h>
#include <cstdint>

#define TOK    65536
#define CDIM   256
#define HID    1024

// ---------------------------------------------------------------------------
// Scratch
// ---------------------------------------------------------------------------
__device__ __half g_xqk [TOK*CDIM];
__device__ __half g_xv  [TOK*CDIM];
__device__ __half g_q   [TOK*CDIM];
__device__ __half g_k   [TOK*CDIM];
__device__ __half g_v   [TOK*CDIM];
__device__ __half g_attn[TOK*CDIM];
__device__ __half g_mo16[TOK*CDIM];
__device__ __half g_x16 [TOK*CDIM];
__device__ __half g_h   [TOK*HID];
__device__ __half g_ff16[TOK*CDIM];
// fp16 weights + pos
__device__ __half g_wl [768*256];
__device__ __half g_wol[256*256];
__device__ __half g_ws [768*256];
__device__ __half g_wos[256*256];
__device__ __half g_w1h[HID*256];
__device__ __half g_w2h[256*HID];
__device__ __half g_pos16[8192*256];

// ---------------------------------------------------------------------------
// PTX helpers
// ---------------------------------------------------------------------------
__device__ __forceinline__ void cpasync16(uint32_t dst, const void* src) {
    asm volatile("cp.async.cg.shared.global [%0], [%1], 16;\n" :: "r"(dst), "l"(src));
}
__device__ __forceinline__ void cp_commit() {
    asm volatile("cp.async.commit_group;\n");
}
template<int N>
__device__ __forceinline__ void cp_wait() {
    asm volatile("cp.async.wait_group %0;\n" :: "n"(N));
}
__device__ __forceinline__ void ldsm4(uint32_t& r0, uint32_t& r1,
                                      uint32_t& r2, uint32_t& r3, uint32_t addr) {
    asm volatile("ldmatrix.sync.aligned.m8n8.x4.shared.b16 {%0,%1,%2,%3}, [%4];"
                 : "=r"(r0), "=r"(r1), "=r"(r2), "=r"(r3) : "r"(addr));
}
__device__ __forceinline__ void ldsm4t(uint32_t& r0, uint32_t& r1,
                                       uint32_t& r2, uint32_t& r3, uint32_t addr) {
    asm volatile("ldmatrix.sync.aligned.m8n8.x4.trans.shared.b16 {%0,%1,%2,%3}, [%4];"
                 : "=r"(r0), "=r"(r1), "=r"(r2), "=r"(r3) : "r"(addr));
}
__device__ __forceinline__ void mma16816(float c[4],
    uint32_t a0, uint32_t a1, uint32_t a2, uint32_t a3, uint32_t b0, uint32_t b1)
{
    asm volatile(
        "mma.sync.aligned.m16n8k16.row.col.f32.f16.f16.f32 "
        "{%0,%1,%2,%3}, {%4,%5,%6,%7}, {%8,%9}, {%0,%1,%2,%3};"
        : "+f"(c[0]), "+f"(c[1]), "+f"(c[2]), "+f"(c[3])
        : "r"(a0), "r"(a1), "r"(a2), "r"(a3), "r"(b0), "r"(b1));
}
__device__ __forceinline__ uint32_t pack2(float a, float b) {
    __half2 h = __floats2half2_rn(a, b);
    return *(uint32_t*)&h;
}

// short-layout permutation: long-flat token f -> (short token ts, pos index n)
__device__ __forceinline__ void fmap_short(int f, int& ts, int& n) {
    int b2 = f >> 13, bh2 = (f >> 10) & 7, h2 = (f >> 6) & 15;
    int w2 = (f >> 3) & 7, ww2 = f & 7;
    ts = (h2*8 + ww2)*512 + b2*64 + bh2*8 + w2;
    int Lf = f >> 10, r = f & 1023;
    int bh = Lf >> 3, w = Lf & 7, hh = (r >> 3) & 15, ww = r & 7;
    n = bh*1024 + hh*64 + w*8 + ww;
}

// ===========================================================================
// DEEP-PIPELINE FP16 GEMM for K=256: 32-half chunks (64B rows), 6 stages,
// prefetch depth 5. 128x128 tile, 8 warps, 2 CTAs/SM.
// EPI: 0 plain, 1 ReLU, 2 fused-QKV split, 3 fused short-gather scatter
// ===========================================================================
#define STG32 16384              // A(8KB) + B(8KB) per stage
#define G32_SMEM (6*STG32)       // 98304

__device__ __forceinline__ void load_chunk32(const __half* __restrict__ A,
                                             const __half* __restrict__ B,
                                             int bm, int bn, int K, int kt,
                                             uint32_t sbase, int tid)
{
    #pragma unroll
    for (int j = 0; j < 2; j++) {
        int idx = tid*2 + j;
        int row = idx >> 2, c = idx & 3;
        uint32_t off = (uint32_t)(row*64 + ((c ^ (row & 3)) << 4));
        cpasync16(sbase + off, A + (size_t)(bm + row)*K + kt*32 + c*8);
    }
    #pragma unroll
    for (int j = 0; j < 2; j++) {
        int idx = tid*2 + j;
        int row = idx >> 2, c = idx & 3;
        uint32_t off = (uint32_t)(row*64 + ((c ^ (row & 3)) << 4));
        cpasync16(sbase + 8192 + off, B + (size_t)(bn + row)*K + kt*32 + c*8);
    }
    cp_commit();
}

template<int EPI, int KT>   // KT = K/32
__global__ void __launch_bounds__(256, 2)
gemm32(const __half* __restrict__ A0, const __half* __restrict__ A1,
       const __half* __restrict__ B,  const float* __restrict__ bias,
       const __half* __restrict__ pos16,
       void* C0, void* C1, void* C2, int N)
{
    constexpr int K = KT * 32;
    extern __shared__ __align__(128) char dsm[];
    const int tid = threadIdx.x;
    const int bm  = blockIdx.x * 128;
    const int bnG = blockIdx.y * 128;

    const __half* A = A0;
    if (EPI == 2) A = (blockIdx.y < 4) ? A0 : A1;

    uint32_t sb = (uint32_t)__cvta_generic_to_shared(dsm);

    const int lane = tid & 31, wid = tid >> 5;
    const int wm = (wid >> 2) * 64;
    const int wn = (wid & 3) * 32;
    const int lq = lane >> 3;
    const int l7 = lane & 7;

    float acc[4][4][4];
    #pragma unroll
    for (int mi = 0; mi < 4; mi++)
        #pragma unroll
        for (int ni = 0; ni < 4; ni++)
            #pragma unroll
            for (int r = 0; r < 4; r++) acc[mi][ni][r] = 0.f;

    // prologue: chunks 0..4
    #pragma unroll
    for (int c = 0; c < 5; c++)
        load_chunk32(A, B, bm, bnG, K, c, sb + (uint32_t)c*STG32, tid);

    int arow[4], brow[2];
    #pragma unroll
    for (int mi = 0; mi < 4; mi++) arow[mi] = wm + mi*16 + (lq & 1)*8 + l7;
    #pragma unroll
    for (int p = 0; p < 2; p++)    brow[p]  = wn + p*16 + (lq >> 1)*8 + l7;
    const int aqh = lq >> 1;
    const int bqh = lq & 1;

    #pragma unroll
    for (int kt = 0; kt < KT; kt++) {
        if      (kt + 5 < KT) cp_wait<4>();
        else if (kt + 4 < KT) cp_wait<3>();
        else if (kt + 3 < KT) cp_wait<2>();
        else if (kt + 2 < KT) cp_wait<1>();
        else                  cp_wait<0>();
        __syncthreads();
        if (kt + 5 < KT)
            load_chunk32(A, B, bm, bnG, K, kt + 5,
                         sb + (uint32_t)((kt + 5) % 6)*STG32, tid);

        uint32_t Ab = sb + (uint32_t)(kt % 6)*STG32;
        uint32_t Bb = Ab + 8192;

        #pragma unroll
        for (int s = 0; s < 2; s++) {
            uint32_t af[4][4];
            #pragma unroll
            for (int mi = 0; mi < 4; mi++) {
                int row = arow[mi];
                uint32_t addr = Ab + (uint32_t)(row*64 +
                                (((2*s + aqh) ^ (row & 3)) << 4));
                ldsm4(af[mi][0], af[mi][1], af[mi][2], af[mi][3], addr);
            }
            uint32_t bf[4][2];
            #pragma unroll
            for (int p = 0; p < 2; p++) {
                int row = brow[p];
                uint32_t addr = Bb + (uint32_t)(row*64 +
                                (((2*s + bqh) ^ (row & 3)) << 4));
                ldsm4(bf[2*p][0], bf[2*p][1], bf[2*p+1][0], bf[2*p+1][1], addr);
            }
            #pragma unroll
            for (int mi = 0; mi < 4; mi++)
                #pragma unroll
                for (int ni = 0; ni < 4; ni++)
                    mma16816(acc[mi][ni], af[mi][0], af[mi][1], af[mi][2], af[mi][3],
                             bf[ni][0], bf[ni][1]);
        }
    }

    const int g2 = lane >> 2, t2 = lane & 3;

    if (EPI == 3) {
        __half* xqk = (__half*)C0;
        __half* xv  = (__half*)C1;
        #pragma unroll
        for (int mi = 0; mi < 4; mi++) {
            int f0 = bm + wm + mi*16 + g2;
            int f1 = f0 + 8;
            int ts0, n0, ts1, n1;
            fmap_short(f0, ts0, n0);
            fmap_short(f1, ts1, n1);
            #pragma unroll
            for (int ni = 0; ni < 4; ni++) {
                int cg = bnG + wn + ni*8 + t2*2;
                float b0 = bias[cg], b1 = bias[cg + 1];
                float v0 = acc[mi][ni][0] + b0;
                float v1 = acc[mi][ni][1] + b1;
                float v2 = acc[mi][ni][2] + b0;
                float v3 = acc[mi][ni][3] + b1;
                float2 p0 = __half22float2(*(const __half2*)&pos16[(size_t)n0*256 + cg]);
                float2 p1 = __half22float2(*(const __half2*)&pos16[(size_t)n1*256 + cg]);
                *(__half2*)&xv [(size_t)ts0*256 + cg] = __floats2half2_rn(v0, v1);
                *(__half2*)&xv [(size_t)ts1*256 + cg] = __floats2half2_rn(v2, v3);
                *(__half2*)&xqk[(size_t)ts0*256 + cg] = __floats2half2_rn(v0+p0.x, v1+p0.y);
                *(__half2*)&xqk[(size_t)ts1*256 + cg] = __floats2half2_rn(v2+p1.x, v3+p1.y);
            }
        }
        return;
    }

    void* dstp = C0;
    int ldc = N, colbase = bnG;
    if (EPI == 2) {
        int region = blockIdx.y >> 1;
        dstp = (region == 0) ? C0 : (region == 1 ? C1 : C2);
        ldc = 256;
        colbase = (blockIdx.y & 1) * 128;
    }

    #pragma unroll
    for (int mi = 0; mi < 4; mi++) {
        #pragma unroll
        for (int ni = 0; ni < 4; ni++) {
            int row = bm + wm + mi*16 + g2;
            int cg  = bnG + wn + ni*8 + t2*2;
            int cl  = colbase + wn + ni*8 + t2*2;
            float b0 = bias[cg], b1 = bias[cg + 1];
            float v0 = acc[mi][ni][0] + b0;
            float v1 = acc[mi][ni][1] + b1;
            float v2 = acc[mi][ni][2] + b0;
            float v3 = acc[mi][ni][3] + b1;
            if (EPI == 1) {
                v0 = fmaxf(v0, 0.f); v1 = fmaxf(v1, 0.f);
                v2 = fmaxf(v2, 0.f); v3 = fmaxf(v3, 0.f);
            }
            __half* d = (__half*)dstp;
            *(__half2*)&d[(size_t)row      *ldc + cl] = __floats2half2_rn(v0, v1);
            *(__half2*)&d[(size_t)(row + 8)*ldc + cl] = __floats2half2_rn(v2, v3);
        }
    }
}

// ===========================================================================
// Proven 64-chunk 3-stage GEMM, kept for FFN2 (K=1024, steady-state)
// ===========================================================================
#define STAGE_B 32768
#define GEMMH_SMEM (3*STAGE_B)

__device__ __forceinline__ void load_chunk16(const __half* __restrict__ A,
                                             const __half* __restrict__ B,
                                             int bm, int bn, int K, int kt,
                                             uint32_t sbase, int tid)
{
    #pragma unroll
    for (int j = 0; j < 4; j++) {
        int idx = tid*4 + j;
        int row = idx >> 3, c = idx & 7;
        uint32_t off = (uint32_t)(row*128 + ((c ^ (row & 7)) << 4));
        cpasync16(sbase + off, A + (size_t)(bm + row)*K + kt*64 + c*8);
    }
    #pragma unroll
    for (int j = 0; j < 4; j++) {
        int idx = tid*4 + j;
        int row = idx >> 3, c = idx & 7;
        uint32_t off = (uint32_t)(row*128 + ((c ^ (row & 7)) << 4));
        cpasync16(sbase + 16384 + off, B + (size_t)(bn + row)*K + kt*64 + c*8);
    }
    cp_commit();
}

template<int KT>
__global__ void __launch_bounds__(256, 2)
gemm_h(const __half* __restrict__ A0, const __half* __restrict__ B,
       const float* __restrict__ bias,
       void* C0, int N)
{
    constexpr int K = KT * 64;
    extern __shared__ __align__(128) char dsm[];
    const int tid = threadIdx.x;
    const int bm  = blockIdx.x * 128;
    const int bnG = blockIdx.y * 128;
    const __half* A = A0;

    uint32_t sb = (uint32_t)__cvta_generic_to_shared(dsm);

    const int lane = tid & 31, wid = tid >> 5;
    const int wm = (wid >> 2) * 64;
    const int wn = (wid & 3) * 32;
    const int lq = lane >> 3;
    const int l7 = lane & 7;

    float acc[4][4][4];
    #pragma unroll
    for (int mi = 0; mi < 4; mi++)
        #pragma unroll
        for (int ni = 0; ni < 4; ni++)
            #pragma unroll
            for (int r = 0; r < 4; r++) acc[mi][ni][r] = 0.f;

    load_chunk16(A, B, bm, bnG, K, 0, sb,           tid);
    load_chunk16(A, B, bm, bnG, K, 1, sb + STAGE_B, tid);

    int arow[4], brow[2];
    #pragma unroll
    for (int mi = 0; mi < 4; mi++) arow[mi] = wm + mi*16 + (lq & 1)*8 + l7;
    #pragma unroll
    for (int p = 0; p < 2; p++)    brow[p]  = wn + p*16 + (lq >> 1)*8 + l7;
    const int aqh = lq >> 1;
    const int bqh = lq & 1;

    #pragma unroll
    for (int kt = 0; kt < KT; kt++) {
        if (kt + 2 < KT) cp_wait<1>(); else cp_wait<0>();
        __syncthreads();
        if (kt + 2 < KT)
            load_chunk16(A, B, bm, bnG, K, kt + 2,
                         sb + (uint32_t)((kt + 2) % 3)*STAGE_B, tid);

        uint32_t Ab = sb + (uint32_t)(kt % 3)*STAGE_B;
        uint32_t Bb = Ab + 16384;

        #pragma unroll
        for (int s = 0; s < 4; s++) {
            uint32_t af[4][4];
            #pragma unroll
            for (int mi = 0; mi < 4; mi++) {
                int row = arow[mi];
                uint32_t addr = Ab + (uint32_t)(row*128 +
                                (((2*s + aqh) ^ (row & 7)) << 4));
                ldsm4(af[mi][0], af[mi][1], af[mi][2], af[mi][3], addr);
            }
            uint32_t bf[4][2];
            #pragma unroll
            for (int p = 0; p < 2; p++) {
                int row = brow[p];
                uint32_t addr = Bb + (uint32_t)(row*128 +
                                (((2*s + bqh) ^ (row & 7)) << 4));
                ldsm4(bf[2*p][0], bf[2*p][1], bf[2*p+1][0], bf[2*p+1][1], addr);
            }
            #pragma unroll
            for (int mi = 0; mi < 4; mi++)
                #pragma unroll
                for (int ni = 0; ni < 4; ni++)
                    mma16816(acc[mi][ni], af[mi][0], af[mi][1], af[mi][2], af[mi][3],
                             bf[ni][0], bf[ni][1]);
        }
    }

    const int g2 = lane >> 2, t2 = lane & 3;
    __half* d = (__half*)C0;
    #pragma unroll
    for (int mi = 0; mi < 4; mi++) {
        #pragma unroll
        for (int ni = 0; ni < 4; ni++) {
            int row = bm + wm + mi*16 + g2;
            int cg  = bnG + wn + ni*8 + t2*2;
            float b0 = bias[cg], b1 = bias[cg + 1];
            *(__half2*)&d[(size_t)row      *N + cg] =
                __floats2half2_rn(acc[mi][ni][0] + b0, acc[mi][ni][1] + b1);
            *(__half2*)&d[(size_t)(row + 8)*N + cg] =
                __floats2half2_rn(acc[mi][ni][2] + b0, acc[mi][ni][3] + b1);
        }
    }
}

// ---------------------------------------------------------------------------
// Merged prep kernel (weights+pos fp16 conversion, long gather)
// ---------------------------------------------------------------------------
__global__ void __launch_bounds__(256)
prep_all(const float* __restrict__ wl, const float* __restrict__ wol,
         const float* __restrict__ ws, const float* __restrict__ wos,
         const float* __restrict__ w1, const float* __restrict__ w2,
         const float* __restrict__ pos, const float* __restrict__ src,
         __half* __restrict__ xqk, __half* __restrict__ xv)
{
    int blk = blockIdx.x;
    if (blk < 3072) {
        const float* s; __half* d;
        if      (blk < 192)  { s = wl;  d = g_wl;               }
        else if (blk < 256)  { s = wol; d = g_wol; blk -= 192;  }
        else if (blk < 448)  { s = ws;  d = g_ws;  blk -= 256;  }
        else if (blk < 512)  { s = wos; d = g_wos; blk -= 448;  }
        else if (blk < 768)  { s = w1;  d = g_w1h; blk -= 512;  }
        else if (blk < 1024) { s = w2;  d = g_w2h; blk -= 768;  }
        else                 { s = pos; d = g_pos16; blk -= 1024; }
        int i = (blk*256 + threadIdx.x) * 4;
        float4 v = *(const float4*)(s + i);
        uint2 o; o.x = pack2(v.x, v.y); o.y = pack2(v.z, v.w);
        *(uint2*)(d + i) = o;
        return;
    }
    blk -= 3072;
    int t  = blk * 4 + (threadIdx.x >> 6);
    int c4 = (threadIdx.x & 63) * 4;
    int Lc = t >> 10, Bt = t & 1023;
    int bh = Lc >> 3, w = Lc & 7;
    int b  = Bt >> 7, hh = (Bt >> 3) & 15, ww = Bt & 7;
    int n  = bh*1024 + hh*64 + w*8 + ww;
    float4 s4 = *(const float4*)(src + ((size_t)b*8192 + n)*256 + c4);
    float4 p4 = *(const float4*)(pos + (size_t)n*256 + c4);
    uint2 ov; ov.x = pack2(s4.x, s4.y); ov.y = pack2(s4.z, s4.w);
    *(uint2*)(xv + (size_t)t*256 + c4) = ov;
    uint2 oq; oq.x = pack2(s4.x+p4.x, s4.y+p4.y); oq.y = pack2(s4.z+p4.z, s4.w+p4.w);
    *(uint2*)(xqk + (size_t)t*256 + c4) = oq;
}

// ---------------------------------------------------------------------------
// Tensor-core attention, two heads per CTA (R8-proven)
// ---------------------------------------------------------------------------
template<int L>
__global__ void __launch_bounds__(4*L)
attn_tc2(const __half* __restrict__ Q, const __half* __restrict__ K,
         const __half* __restrict__ V, __half* __restrict__ O, int BtC)
{
    constexpr int WPH = L/16;
    __shared__ __align__(128) __half sQ[L*64];
    __shared__ __align__(128) __half sK[L*64];
    __shared__ __align__(128) __half sV[L*64];

    const int bt   = blockIdx.x % BtC;
    const int hp   = blockIdx.x / BtC;
    const int tid  = threadIdx.x;
    const int lane = tid & 31, w = tid >> 5;
    const int hh   = w / WPH;
    const int wi   = w % WPH;
    const float scale = 0.17677669529663687f;

    uint32_t bq = (uint32_t)__cvta_generic_to_shared(sQ);
    uint32_t bk = (uint32_t)__cvta_generic_to_shared(sK);
    uint32_t bv = (uint32_t)__cvta_generic_to_shared(sV);

    #pragma unroll
    for (int seg = tid; seg < L*8; seg += 4*L) {
        int l = seg >> 3, u = seg & 7;
        size_t g = ((size_t)l * BtC + bt) * 256 + hp*64 + u*8;
        uint32_t so = (uint32_t)(l*128 + ((u ^ (l & 7)) << 4));
        cpasync16(bq + so, Q + g);
        cpasync16(bk + so, K + g);
        cpasync16(bv + so, V + g);
    }
    cp_commit();
    cp_wait<0>();
    __syncthreads();

    float sa[L/8][4];
    #pragma unroll
    for (int ni = 0; ni < L/8; ni++)
        #pragma unroll
        for (int r = 0; r < 4; r++) sa[ni][r] = 0.f;

    uint32_t a[2][4];
    {
        int arow = wi*16 + (lane & 15);
        uint32_t ab = bq + (uint32_t)(arow*128);
        #pragma unroll
        for (int s = 0; s < 2; s++) {
            int unit = hh*4 + 2*s + (lane >> 4);
            ldsm4(a[s][0], a[s][1], a[s][2], a[s][3],
                  ab + (uint32_t)((unit ^ (arow & 7)) << 4));
        }
    }
    {
        int br7 = (lane & 7) + ((lane >> 4) << 3);
        int bu  = (lane >> 3) & 1;
        #pragma unroll
        for (int j = 0; j < L/16; j++) {
            int row = j*16 + br7;
            uint32_t rb = bk + (uint32_t)(row*128);
            #pragma unroll
            for (int s = 0; s < 2; s++) {
                int unit = hh*4 + 2*s + bu;
                uint32_t b0, b1, b2, b3;
                ldsm4(b0, b1, b2, b3, rb + (uint32_t)((unit ^ (row & 7)) << 4));
                mma16816(sa[2*j],   a[s][0], a[s][1], a[s][2], a[s][3], b0, b1);
                mma16816(sa[2*j+1], a[s][0], a[s][1], a[s][2], a[s][3], b2, b3);
            }
        }
    }

    float mlo = -1e30f, mhi = -1e30f;
    #pragma unroll
    for (int ni = 0; ni < L/8; ni++) {
        mlo = fmaxf(mlo, fmaxf(sa[ni][0], sa[ni][1]));
        mhi = fmaxf(mhi, fmaxf(sa[ni][2], sa[ni][3]));
    }
    #pragma unroll
    for (int o = 1; o <= 2; o <<= 1) {
        mlo = fmaxf(mlo, __shfl_xor_sync(~0u, mlo, o));
        mhi = fmaxf(mhi, __shfl_xor_sync(~0u, mhi, o));
    }
    float slo = 0.f, shi = 0.f;
    #pragma unroll
    for (int ni = 0; ni < L/8; ni++) {
        float e0 = __expf((sa[ni][0] - mlo) * scale);
        float e1 = __expf((sa[ni][1] - mlo) * scale);
        float e2 = __expf((sa[ni][2] - mhi) * scale);
        float e3 = __expf((sa[ni][3] - mhi) * scale);
        sa[ni][0] = e0; sa[ni][1] = e1; sa[ni][2] = e2; sa[ni][3] = e3;
        slo += e0 + e1; shi += e2 + e3;
    }
    #pragma unroll
    for (int o = 1; o <= 2; o <<= 1) {
        slo += __shfl_xor_sync(~0u, slo, o);
        shi += __shfl_xor_sync(~0u, shi, o);
    }
    const float ilo = 1.f / slo, ihi = 1.f / shi;

    float oa[4][4];
    #pragma unroll
    for (int ni = 0; ni < 4; ni++)
        #pragma unroll
        for (int r = 0; r < 4; r++) oa[ni][r] = 0.f;

    {
        int vr7 = (lane & 7) + (((lane >> 3) & 1) << 3);
        int vu  = lane >> 4;
        #pragma unroll
        for (int s = 0; s < L/16; s++) {
            int row = s*16 + vr7;
            uint32_t rb = bv + (uint32_t)(row*128);
            int u1 = hh*4 + vu, u2 = hh*4 + vu + 2;
            uint32_t v0,v1,v2,v3,v4,v5,v6,v7;
            ldsm4t(v0, v1, v2, v3, rb + (uint32_t)((u1 ^ (row & 7)) << 4));
            ldsm4t(v4, v5, v6, v7, rb + (uint32_t)((u2 ^ (row & 7)) << 4));
            uint32_t a0 = pack2(sa[2*s  ][0], sa[2*s  ][1]);
            uint32_t a1 = pack2(sa[2*s  ][2], sa[2*s  ][3]);
            uint32_t a2 = pack2(sa[2*s+1][0], sa[2*s+1][1]);
            uint32_t a3 = pack2(sa[2*s+1][2], sa[2*s+1][3]);
            mma16816(oa[0], a0, a1, a2, a3, v0, v1);
            mma16816(oa[1], a0, a1, a2, a3, v2, v3);
            mma16816(oa[2], a0, a1, a2, a3, v4, v5);
            mma16816(oa[3], a0, a1, a2, a3, v6, v7);
        }
    }

    {
        int g2 = lane >> 2, t2 = (lane & 3) * 2;
        int h  = hp*2 + hh;
        int rlo = wi*16 + g2, rhi = rlo + 8;
        size_t glo = ((size_t)rlo * BtC + bt) * 256 + h*32 + t2;
        size_t ghi = ((size_t)rhi * BtC + bt) * 256 + h*32 + t2;
        #pragma unroll
        for (int ni = 0; ni < 4; ni++) {
            *(__half2*)&O[glo + ni*8] = __floats2half2_rn(oa[ni][0]*ilo, oa[ni][1]*ilo);
            *(__half2*)&O[ghi + ni*8] = __floats2half2_rn(oa[ni][2]*ihi, oa[ni][3]*ihi);
        }
    }
}

// ---------------------------------------------------------------------------
// Residual + scatter + LayerNorm1 (vectorized)
// ---------------------------------------------------------------------------
__global__ void __launch_bounds__(256)
resid_ln1(const float* __restrict__ src, const __half* __restrict__ mo,
          const float* __restrict__ g, const float* __restrict__ be,
          __half* __restrict__ out16)
{
    int tok  = blockIdx.x * 8 + (threadIdx.x >> 5);
    int lane = threadIdx.x & 31;
    int b = tok >> 13, n = tok & 8191;
    int h2 = n >> 9, bh2 = (n >> 6) & 7, ww2 = (n >> 3) & 7, w2 = n & 7;
    int ts = (h2*8 + ww2)*512 + b*64 + bh2*8 + w2;
    const float*  xs = src + (size_t)tok*256 + lane*8;
    const __half* ms = mo  + (size_t)ts *256 + lane*8;

    float4 x0 = *(const float4*)(xs);
    float4 x1 = *(const float4*)(xs + 4);
    uint2  m2 = *(const uint2*)(ms);
    uint2  m3 = *(const uint2*)(ms + 4);
    __half2 ma = *(__half2*)&m2.x, mb = *(__half2*)&m2.y;
    __half2 mc = *(__half2*)&m3.x, md = *(__half2*)&m3.y;
    float2 fa = __half22float2(ma), fb = __half22float2(mb);
    float2 fc = __half22float2(mc), fd = __half22float2(md);

    float v[8];
    v[0] = x0.x + fa.x; v[1] = x0.y + fa.y;
    v[2] = x0.z + fb.x; v[3] = x0.w + fb.y;
    v[4] = x1.x + fc.x; v[5] = x1.y + fc.y;
    v[6] = x1.z + fd.x; v[7] = x1.w + fd.y;

    float sum = 0.f, sq = 0.f;
    #pragma unroll
    for (int i = 0; i < 8; i++) { sum += v[i]; sq += v[i]*v[i]; }
    #pragma unroll
    for (int o = 16; o; o >>= 1) {
        sum += __shfl_xor_sync(~0u, sum, o);
        sq  += __shfl_xor_sync(~0u, sq , o);
    }
    float mu  = sum * (1.f/256.f);
    float var = sq * (1.f/256.f) - mu*mu;
    float inv = rsqrtf(var + 1e-5f);

    int c0 = lane*8;
    float4 g0 = *(const float4*)(g + c0);
    float4 g1 = *(const float4*)(g + c0 + 4);
    float4 e0 = *(const float4*)(be + c0);
    float4 e1 = *(const float4*)(be + c0 + 4);
    uint4 o4;
    o4.x = pack2((v[0]-mu)*inv*g0.x + e0.x, (v[1]-mu)*inv*g0.y + e0.y);
    o4.y = pack2((v[2]-mu)*inv*g0.z + e0.z, (v[3]-mu)*inv*g0.w + e0.w);
    o4.z = pack2((v[4]-mu)*inv*g1.x + e1.x, (v[5]-mu)*inv*g1.y + e1.y);
    o4.w = pack2((v[6]-mu)*inv*g1.z + e1.z, (v[7]-mu)*inv*g1.w + e1.w);
    *(uint4*)(out16 + (size_t)tok*256 + c0) = o4;
}

// ---------------------------------------------------------------------------
// Fused residual + LayerNorm2 + output transpose (vectorized fp16 inputs)
// ---------------------------------------------------------------------------
__global__ void __launch_bounds__(256)
add_ln_tr(const __half* __restrict__ a, const __half* __restrict__ bsrc,
          const float* __restrict__ g, const float* __restrict__ be,
          float* __restrict__ out)
{
    __shared__ float tile[32][257];
    int blk = blockIdx.x;
    int b = blk >> 8, nb = blk & 255;
    int n0 = nb * 32;
    int w = threadIdx.x >> 5, lane = threadIdx.x & 31;

    int c0 = lane*8;
    float4 gg0 = *(const float4*)(g + c0);
    float4 gg1 = *(const float4*)(g + c0 + 4);
    float4 ee0 = *(const float4*)(be + c0);
    float4 ee1 = *(const float4*)(be + c0 + 4);

    #pragma unroll
    for (int i = 0; i < 4; i++) {
        int lt = w*4 + i;
        size_t tok = (size_t)b*8192 + n0 + lt;
        const __half* xa = a    + tok*256 + c0;
        const __half* xb = bsrc + tok*256 + c0;
        uint4 ua = *(const uint4*)xa;
        uint4 ub = *(const uint4*)xb;
        const __half2* ha = (const __half2*)&ua;
        const __half2* hb = (const __half2*)&ub;
        float v[8];
        #pragma unroll
        for (int e = 0; e < 4; e++) {
            float2 pa = __half22float2(ha[e]);
            float2 pb = __half22float2(hb[e]);
            v[2*e]   = pa.x + pb.x;
            v[2*e+1] = pa.y + pb.y;
        }
        float sum = 0.f, sq = 0.f;
        #pragma unroll
        for (int e = 0; e < 8; e++) { sum += v[e]; sq += v[e]*v[e]; }
        #pragma unroll
        for (int o = 16; o; o >>= 1) {
            sum += __shfl_xor_sync(~0u, sum, o);
            sq  += __shfl_xor_sync(~0u, sq , o);
        }
        float mu  = sum * (1.f/256.f);
        float var = sq * (1.f/256.f) - mu*mu;
        float inv = rsqrtf(var + 1e-5f);
        tile[lt][c0+0] = (v[0]-mu)*inv*gg0.x + ee0.x;
        tile[lt][c0+1] = (v[1]-mu)*inv*gg0.y + ee0.y;
        tile[lt][c0+2] = (v[2]-mu)*inv*gg0.z + ee0.z;
        tile[lt][c0+3] = (v[3]-mu)*inv*gg0.w + ee0.w;
        tile[lt][c0+4] = (v[4]-mu)*inv*gg1.x + ee1.x;
        tile[lt][c0+5] = (v[5]-mu)*inv*gg1.y + ee1.y;
        tile[lt][c0+6] = (v[6]-mu)*inv*gg1.z + ee1.z;
        tile[lt][c0+7] = (v[7]-mu)*inv*gg1.w + ee1.w;
    }
    __syncthreads();

    size_t ob = (size_t)b*2097152 + n0 + lane;
    #pragma unroll
    for (int k = 0; k < 32; k++) {
        int c = w*32 + k;
        out[ob + (size_t)c*8192] = tile[lane][c];
    }
}

// ---------------------------------------------------------------------------
// Launch
// ---------------------------------------------------------------------------
extern "C" void kernel_launch(void* const* d_in, const int* in_sizes, int n_in,
                              void* d_out, int out_size)
{
    const float* src        = (const float*)d_in[0];
    const float* pos        = (const float*)d_in[1];
    const float* w_in_long  = (const float*)d_in[2];
    const float* b_in_long  = (const float*)d_in[3];
    const float* w_out_long = (const float*)d_in[4];
    const float* b_out_long = (const float*)d_in[5];
    const float* w_in_short = (const float*)d_in[6];
    const float* b_in_short = (const float*)d_in[7];
    const float* w_out_short= (const float*)d_in[8];
    const float* b_out_short= (const float*)d_in[9];
    const float* w1         = (const float*)d_in[10];
    const float* b1         = (const float*)d_in[11];
    const float* w2         = (const float*)d_in[12];
    const float* b2         = (const float*)d_in[13];
    const float* g1         = (const float*)d_in[14];
    const float* beta1      = (const float*)d_in[15];
    const float* g2         = (const float*)d_in[16];
    const float* beta2      = (const float*)d_in[17];
    float* out = (float*)d_out;

    static __half *p_xqk=nullptr,*p_xv,*p_q,*p_k,*p_v,*p_attn,*p_mo16,*p_x16,*p_h,*p_ff16;
    static __half *p_wl,*p_wol,*p_ws,*p_wos,*p_w1,*p_w2,*p_pos16;
    static bool init_done = false;
    if (!init_done) {
        cudaGetSymbolAddress((void**)&p_xqk , g_xqk );
        cudaGetSymbolAddress((void**)&p_xv  , g_xv  );
        cudaGetSymbolAddress((void**)&p_q   , g_q   );
        cudaGetSymbolAddress((void**)&p_k   , g_k   );
        cudaGetSymbolAddress((void**)&p_v   , g_v   );
        cudaGetSymbolAddress((void**)&p_attn, g_attn);
        cudaGetSymbolAddress((void**)&p_mo16, g_mo16);
        cudaGetSymbolAddress((void**)&p_x16 , g_x16 );
        cudaGetSymbolAddress((void**)&p_ff16, g_ff16);
        cudaGetSymbolAddress((void**)&p_h   , g_h   );
        cudaGetSymbolAddress((void**)&p_wl  , g_wl  );
        cudaGetSymbolAddress((void**)&p_wol , g_wol );
        cudaGetSymbolAddress((void**)&p_ws  , g_ws  );
        cudaGetSymbolAddress((void**)&p_wos , g_wos );
        cudaGetSymbolAddress((void**)&p_w1  , g_w1h );
        cudaGetSymbolAddress((void**)&p_w2  , g_w2h );
        cudaGetSymbolAddress((void**)&p_pos16, g_pos16);
        cudaFuncSetAttribute((const void*)gemm32<0,8>,
            cudaFuncAttributeMaxDynamicSharedMemorySize, G32_SMEM);
        cudaFuncSetAttribute((const void*)gemm32<1,8>,
            cudaFuncAttributeMaxDynamicSharedMemorySize, G32_SMEM);
        cudaFuncSetAttribute((const void*)gemm32<2,8>,
            cudaFuncAttributeMaxDynamicSharedMemorySize, G32_SMEM);
        cudaFuncSetAttribute((const void*)gemm32<3,8>,
            cudaFuncAttributeMaxDynamicSharedMemorySize, G32_SMEM);
        cudaFuncSetAttribute((const void*)gemm_h<16>,
            cudaFuncAttributeMaxDynamicSharedMemorySize, GEMMH_SMEM);
        init_done = true;
    }

    // ---- fused prep: weight/pos fp16 conversion + long gather ----
    prep_all<<<3072 + TOK/4, 256>>>(w_in_long, w_out_long, w_in_short, w_out_short,
                                    w1, w2, pos, src, p_xqk, p_xv);

    const dim3 gQKV(TOK/128, 6);
    const dim3 g256(TOK/128, 2);
    const dim3 gHID(TOK/128, 8);

    // ---- long-range MHA ----
    gemm32<2,8><<<gQKV, 256, G32_SMEM>>>(p_xqk, p_xv, p_wl, b_in_long, nullptr,
                                         p_q, p_k, p_v, 768);
    attn_tc2<64><<<1024*4, 256>>>(p_q, p_k, p_v, p_attn, 1024);
    gemm32<3,8><<<g256, 256, G32_SMEM>>>(p_attn, nullptr, p_wol, b_out_long, p_pos16,
                                         p_xqk, p_xv, nullptr, 256);

    // ---- short-range MHA ----
    gemm32<2,8><<<gQKV, 256, G32_SMEM>>>(p_xqk, p_xv, p_ws, b_in_short, nullptr,
                                         p_q, p_k, p_v, 768);
    attn_tc2<128><<<512*4, 512>>>(p_q, p_k, p_v, p_attn, 512);
    gemm32<0,8><<<g256, 256, G32_SMEM>>>(p_attn, nullptr, p_wos, b_out_short, nullptr,
                                         p_mo16, nullptr, nullptr, 256);

    // ---- residual + LN1 ----
    resid_ln1<<<TOK/8, 256>>>(src, p_mo16, g1, beta1, p_x16);

    // ---- FFN ----
    gemm32<1,8><<<gHID, 256, G32_SMEM>>>(p_x16, nullptr, p_w1, b1, nullptr,
                                         p_h, nullptr, nullptr, 1024);
    gemm_h<16><<<g256, 256, GEMMH_SMEM>>>(p_h, p_w2, b2, p_ff16, 256);

    // ---- residual + LN2 + output transpose ----
    add_ln_tr<<<2048, 256>>>(p_x16, p_ff16, g2, beta2, out);
}

// round 16
// speedup vs baseline: 1.0815x; 1.0815x over previous
#include <cuda_runtime.h>
#include <cuda_fp16.h>
#include <cstdint>

#define TOK    65536
#define CDIM   256
#define HID    1024

// ---------------------------------------------------------------------------
// Scratch
// ---------------------------------------------------------------------------
__device__ __half g_xqk [TOK*CDIM];
__device__ __half g_xv  [TOK*CDIM];
__device__ __half g_q   [TOK*CDIM];
__device__ __half g_k   [TOK*CDIM];
__device__ __half g_v   [TOK*CDIM];
__device__ __half g_attn[TOK*CDIM];
__device__ __half g_mo16[TOK*CDIM];
__device__ __half g_x16 [TOK*CDIM];
__device__ __half g_h   [TOK*HID];
__device__ __half g_ff16[TOK*CDIM];
// fp16 weights + pos
__device__ __half g_wl [768*256];
__device__ __half g_wol[256*256];
__device__ __half g_ws [768*256];
__device__ __half g_wos[256*256];
__device__ __half g_w1h[HID*256];
__device__ __half g_w2h[256*HID];
__device__ __half g_pos16[8192*256];

// ---------------------------------------------------------------------------
// PTX helpers
// ---------------------------------------------------------------------------
__device__ __forceinline__ void cpasync16(uint32_t dst, const void* src) {
    asm volatile("cp.async.cg.shared.global [%0], [%1], 16;\n" :: "r"(dst), "l"(src));
}
__device__ __forceinline__ void cp_commit() {
    asm volatile("cp.async.commit_group;\n");
}
template<int N>
__device__ __forceinline__ void cp_wait() {
    asm volatile("cp.async.wait_group %0;\n" :: "n"(N));
}
__device__ __forceinline__ void ldsm4(uint32_t& r0, uint32_t& r1,
                                      uint32_t& r2, uint32_t& r3, uint32_t addr) {
    asm volatile("ldmatrix.sync.aligned.m8n8.x4.shared.b16 {%0,%1,%2,%3}, [%4];"
                 : "=r"(r0), "=r"(r1), "=r"(r2), "=r"(r3) : "r"(addr));
}
__device__ __forceinline__ void ldsm4t(uint32_t& r0, uint32_t& r1,
                                       uint32_t& r2, uint32_t& r3, uint32_t addr) {
    asm volatile("ldmatrix.sync.aligned.m8n8.x4.trans.shared.b16 {%0,%1,%2,%3}, [%4];"
                 : "=r"(r0), "=r"(r1), "=r"(r2), "=r"(r3) : "r"(addr));
}
__device__ __forceinline__ void mma16816(float c[4],
    uint32_t a0, uint32_t a1, uint32_t a2, uint32_t a3, uint32_t b0, uint32_t b1)
{
    asm volatile(
        "mma.sync.aligned.m16n8k16.row.col.f32.f16.f16.f32 "
        "{%0,%1,%2,%3}, {%4,%5,%6,%7}, {%8,%9}, {%0,%1,%2,%3};"
        : "+f"(c[0]), "+f"(c[1]), "+f"(c[2]), "+f"(c[3])
        : "r"(a0), "r"(a1), "r"(a2), "r"(a3), "r"(b0), "r"(b1));
}
__device__ __forceinline__ uint32_t pack2(float a, float b) {
    __half2 h = __floats2half2_rn(a, b);
    return *(uint32_t*)&h;
}

// short-layout permutation: long-flat token f -> (short token ts, pos index n)
__device__ __forceinline__ void fmap_short(int f, int& ts, int& n) {
    int b2 = f >> 13, bh2 = (f >> 10) & 7, h2 = (f >> 6) & 15;
    int w2 = (f >> 3) & 7, ww2 = f & 7;
    ts = (h2*8 + ww2)*512 + b2*64 + bh2*8 + w2;
    int Lf = f >> 10, r = f & 1023;
    int bh = Lf >> 3, w = Lf & 7, hh = (r >> 3) & 15, ww = r & 7;
    n = bh*1024 + hh*64 + w*8 + ww;
}

// ---------------------------------------------------------------------------
// FP16 tensor-core GEMM (128x128, 2 CTAs/SM, 3-stage, 1 barrier/chunk)
// KT templated: K = KT*64 known at compile time -> fully unrolled pipeline.
// EPI: 0 plain, 1 ReLU, 2 fused-QKV split, 3 fused short-gather scatter
// OUTH: 1 fp16 C, 0 fp32 C
// ---------------------------------------------------------------------------
#define STAGE_B 32768
#define GEMMH_SMEM (3*STAGE_B)

__device__ __forceinline__ void load_chunk16(const __half* __restrict__ A,
                                             const __half* __restrict__ B,
                                             int bm, int bn, int K, int kt,
                                             uint32_t sbase, int tid)
{
    #pragma unroll
    for (int j = 0; j < 4; j++) {
        int idx = tid*4 + j;
        int row = idx >> 3, c = idx & 7;
        uint32_t off = (uint32_t)(row*128 + ((c ^ (row & 7)) << 4));
        cpasync16(sbase + off, A + (size_t)(bm + row)*K + kt*64 + c*8);
    }
    #pragma unroll
    for (int j = 0; j < 4; j++) {
        int idx = tid*4 + j;
        int row = idx >> 3, c = idx & 7;
        uint32_t off = (uint32_t)(row*128 + ((c ^ (row & 7)) << 4));
        cpasync16(sbase + 16384 + off, B + (size_t)(bn + row)*K + kt*64 + c*8);
    }
    cp_commit();
}

template<int EPI, int OUTH, int KT>
__global__ void __launch_bounds__(256, 2)
gemm_h(const __half* __restrict__ A0, const __half* __restrict__ A1,
       const __half* __restrict__ B,  const float* __restrict__ bias,
       const __half* __restrict__ pos16,
       void* C0, void* C1, void* C2, int N)
{
    constexpr int K = KT * 64;
    extern __shared__ __align__(128) char dsm[];
    const int tid = threadIdx.x;
    const int bm  = blockIdx.x * 128;
    const int bnG = blockIdx.y * 128;

    const __half* A = A0;
    if (EPI == 2) A = (blockIdx.y < 4) ? A0 : A1;

    uint32_t sb = (uint32_t)__cvta_generic_to_shared(dsm);

    const int lane = tid & 31, wid = tid >> 5;
    const int wm = (wid >> 2) * 64;
    const int wn = (wid & 3) * 32;
    const int lq = lane >> 3;
    const int l7 = lane & 7;

    float acc[4][4][4];
    #pragma unroll
    for (int mi = 0; mi < 4; mi++)
        #pragma unroll
        for (int ni = 0; ni < 4; ni++)
            #pragma unroll
            for (int r = 0; r < 4; r++) acc[mi][ni][r] = 0.f;

    load_chunk16(A, B, bm, bnG, K, 0, sb,           tid);
    load_chunk16(A, B, bm, bnG, K, 1, sb + STAGE_B, tid);

    int arow[4], brow[2];
    #pragma unroll
    for (int mi = 0; mi < 4; mi++) arow[mi] = wm + mi*16 + (lq & 1)*8 + l7;
    #pragma unroll
    for (int p = 0; p < 2; p++)    brow[p]  = wn + p*16 + (lq >> 1)*8 + l7;
    const int aqh = lq >> 1;
    const int bqh = lq & 1;

    #pragma unroll
    for (int kt = 0; kt < KT; kt++) {
        if (kt + 2 < KT) cp_wait<1>(); else cp_wait<0>();
        __syncthreads();
        if (kt + 2 < KT)
            load_chunk16(A, B, bm, bnG, K, kt + 2,
                         sb + (uint32_t)((kt + 2) % 3)*STAGE_B, tid);

        uint32_t Ab = sb + (uint32_t)(kt % 3)*STAGE_B;
        uint32_t Bb = Ab + 16384;

        #pragma unroll
        for (int s = 0; s < 4; s++) {
            uint32_t af[4][4];
            #pragma unroll
            for (int mi = 0; mi < 4; mi++) {
                int row = arow[mi];
                uint32_t addr = Ab + (uint32_t)(row*128 +
                                (((2*s + aqh) ^ (row & 7)) << 4));
                ldsm4(af[mi][0], af[mi][1], af[mi][2], af[mi][3], addr);
            }
            uint32_t bf[4][2];
            #pragma unroll
            for (int p = 0; p < 2; p++) {
                int row = brow[p];
                uint32_t addr = Bb + (uint32_t)(row*128 +
                                (((2*s + bqh) ^ (row & 7)) << 4));
                ldsm4(bf[2*p][0], bf[2*p][1], bf[2*p+1][0], bf[2*p+1][1], addr);
            }
            #pragma unroll
            for (int mi = 0; mi < 4; mi++)
                #pragma unroll
                for (int ni = 0; ni < 4; ni++)
                    mma16816(acc[mi][ni], af[mi][0], af[mi][1], af[mi][2], af[mi][3],
                             bf[ni][0], bf[ni][1]);
        }
    }

    const int g2 = lane >> 2, t2 = lane & 3;

    if (EPI == 3) {
        // fused short-gather scatter with fp16 pos
        __half* xqk = (__half*)C0;
        __half* xv  = (__half*)C1;
        #pragma unroll
        for (int mi = 0; mi < 4; mi++) {
            int f0 = bm + wm + mi*16 + g2;
            int f1 = f0 + 8;
            int ts0, n0, ts1, n1;
            fmap_short(f0, ts0, n0);
            fmap_short(f1, ts1, n1);
            #pragma unroll
            for (int ni = 0; ni < 4; ni++) {
                int cg = bnG + wn + ni*8 + t2*2;
                float b0 = bias[cg], b1 = bias[cg + 1];
                float v0 = acc[mi][ni][0] + b0;
                float v1 = acc[mi][ni][1] + b1;
                float v2 = acc[mi][ni][2] + b0;
                float v3 = acc[mi][ni][3] + b1;
                float2 p0 = __half22float2(*(const __half2*)&pos16[(size_t)n0*256 + cg]);
                float2 p1 = __half22float2(*(const __half2*)&pos16[(size_t)n1*256 + cg]);
                *(__half2*)&xv [(size_t)ts0*256 + cg] = __floats2half2_rn(v0, v1);
                *(__half2*)&xv [(size_t)ts1*256 + cg] = __floats2half2_rn(v2, v3);
                *(__half2*)&xqk[(size_t)ts0*256 + cg] = __floats2half2_rn(v0+p0.x, v1+p0.y);
                *(__half2*)&xqk[(size_t)ts1*256 + cg] = __floats2half2_rn(v2+p1.x, v3+p1.y);
            }
        }
        return;
    }

    void* dstp = C0;
    int ldc = N, colbase = bnG;
    if (EPI == 2) {
        int region = blockIdx.y >> 1;
        dstp = (region == 0) ? C0 : (region == 1 ? C1 : C2);
        ldc = 256;
        colbase = (blockIdx.y & 1) * 128;
    }

    #pragma unroll
    for (int mi = 0; mi < 4; mi++) {
        #pragma unroll
        for (int ni = 0; ni < 4; ni++) {
            int row = bm + wm + mi*16 + g2;
            int cg  = bnG + wn + ni*8 + t2*2;
            int cl  = colbase + wn + ni*8 + t2*2;
            float b0 = bias[cg], b1 = bias[cg + 1];
            float v0 = acc[mi][ni][0] + b0;
            float v1 = acc[mi][ni][1] + b1;
            float v2 = acc[mi][ni][2] + b0;
            float v3 = acc[mi][ni][3] + b1;
            if (EPI == 1) {
                v0 = fmaxf(v0, 0.f); v1 = fmaxf(v1, 0.f);
                v2 = fmaxf(v2, 0.f); v3 = fmaxf(v3, 0.f);
            }
            if (OUTH) {
                __half* d = (__half*)dstp;
                *(__half2*)&d[(size_t)row      *ldc + cl] = __floats2half2_rn(v0, v1);
                *(__half2*)&d[(size_t)(row + 8)*ldc + cl] = __floats2half2_rn(v2, v3);
            } else {
                float* d = (float*)dstp;
                *(float2*)&d[(size_t)row      *ldc + cl] = make_float2(v0, v1);
                *(float2*)&d[(size_t)(row + 8)*ldc + cl] = make_float2(v2, v3);
            }
        }
    }
}

// ---------------------------------------------------------------------------
// Merged prep kernel: blocks [0,3072) convert weights+pos to fp16;
// blocks [3072, 3072+16384) do the long gather (src -> xqk/xv with +pos).
// ---------------------------------------------------------------------------
__global__ void __launch_bounds__(256)
prep_all(const float* __restrict__ wl, const float* __restrict__ wol,
         const float* __restrict__ ws, const float* __restrict__ wos,
         const float* __restrict__ w1, const float* __restrict__ w2,
         const float* __restrict__ pos, const float* __restrict__ src,
         __half* __restrict__ xqk, __half* __restrict__ xv)
{
    int blk = blockIdx.x;
    if (blk < 3072) {
        const float* s; __half* d;
        if      (blk < 192)  { s = wl;  d = g_wl;               }
        else if (blk < 256)  { s = wol; d = g_wol; blk -= 192;  }
        else if (blk < 448)  { s = ws;  d = g_ws;  blk -= 256;  }
        else if (blk < 512)  { s = wos; d = g_wos; blk -= 448;  }
        else if (blk < 768)  { s = w1;  d = g_w1h; blk -= 512;  }
        else if (blk < 1024) { s = w2;  d = g_w2h; blk -= 768;  }
        else                 { s = pos; d = g_pos16; blk -= 1024; }
        int i = (blk*256 + threadIdx.x) * 4;
        float4 v = *(const float4*)(s + i);
        uint2 o; o.x = pack2(v.x, v.y); o.y = pack2(v.z, v.w);
        *(uint2*)(d + i) = o;
        return;
    }
    blk -= 3072;
    int t  = blk * 4 + (threadIdx.x >> 6);
    int c4 = (threadIdx.x & 63) * 4;
    int Lc = t >> 10, Bt = t & 1023;
    int bh = Lc >> 3, w = Lc & 7;
    int b  = Bt >> 7, hh = (Bt >> 3) & 15, ww = Bt & 7;
    int n  = bh*1024 + hh*64 + w*8 + ww;
    float4 s4 = *(const float4*)(src + ((size_t)b*8192 + n)*256 + c4);
    float4 p4 = *(const float4*)(pos + (size_t)n*256 + c4);
    uint2 ov; ov.x = pack2(s4.x, s4.y); ov.y = pack2(s4.z, s4.w);
    *(uint2*)(xv + (size_t)t*256 + c4) = ov;
    uint2 oq; oq.x = pack2(s4.x+p4.x, s4.y+p4.y); oq.y = pack2(s4.z+p4.z, s4.w+p4.w);
    *(uint2*)(xqk + (size_t)t*256 + c4) = oq;
}

// ---------------------------------------------------------------------------
// Tensor-core attention, two heads per CTA (R8-proven)
// ---------------------------------------------------------------------------
template<int L>
__global__ void __launch_bounds__(4*L)
attn_tc2(const __half* __restrict__ Q, const __half* __restrict__ K,
         const __half* __restrict__ V, __half* __restrict__ O, int BtC)
{
    constexpr int WPH = L/16;
    __shared__ __align__(128) __half sQ[L*64];
    __shared__ __align__(128) __half sK[L*64];
    __shared__ __align__(128) __half sV[L*64];

    const int bt   = blockIdx.x % BtC;
    const int hp   = blockIdx.x / BtC;
    const int tid  = threadIdx.x;
    const int lane = tid & 31, w = tid >> 5;
    const int hh   = w / WPH;
    const int wi   = w % WPH;
    const float scale = 0.17677669529663687f;

    uint32_t bq = (uint32_t)__cvta_generic_to_shared(sQ);
    uint32_t bk = (uint32_t)__cvta_generic_to_shared(sK);
    uint32_t bv = (uint32_t)__cvta_generic_to_shared(sV);

    #pragma unroll
    for (int seg = tid; seg < L*8; seg += 4*L) {
        int l = seg >> 3, u = seg & 7;
        size_t g = ((size_t)l * BtC + bt) * 256 + hp*64 + u*8;
        uint32_t so = (uint32_t)(l*128 + ((u ^ (l & 7)) << 4));
        cpasync16(bq + so, Q + g);
        cpasync16(bk + so, K + g);
        cpasync16(bv + so, V + g);
    }
    cp_commit();
    cp_wait<0>();
    __syncthreads();

    float sa[L/8][4];
    #pragma unroll
    for (int ni = 0; ni < L/8; ni++)
        #pragma unroll
        for (int r = 0; r < 4; r++) sa[ni][r] = 0.f;

    uint32_t a[2][4];
    {
        int arow = wi*16 + (lane & 15);
        uint32_t ab = bq + (uint32_t)(arow*128);
        #pragma unroll
        for (int s = 0; s < 2; s++) {
            int unit = hh*4 + 2*s + (lane >> 4);
            ldsm4(a[s][0], a[s][1], a[s][2], a[s][3],
                  ab + (uint32_t)((unit ^ (arow & 7)) << 4));
        }
    }
    {
        int br7 = (lane & 7) + ((lane >> 4) << 3);
        int bu  = (lane >> 3) & 1;
        #pragma unroll
        for (int j = 0; j < L/16; j++) {
            int row = j*16 + br7;
            uint32_t rb = bk + (uint32_t)(row*128);
            #pragma unroll
            for (int s = 0; s < 2; s++) {
                int unit = hh*4 + 2*s + bu;
                uint32_t b0, b1, b2, b3;
                ldsm4(b0, b1, b2, b3, rb + (uint32_t)((unit ^ (row & 7)) << 4));
                mma16816(sa[2*j],   a[s][0], a[s][1], a[s][2], a[s][3], b0, b1);
                mma16816(sa[2*j+1], a[s][0], a[s][1], a[s][2], a[s][3], b2, b3);
            }
        }
    }

    float mlo = -1e30f, mhi = -1e30f;
    #pragma unroll
    for (int ni = 0; ni < L/8; ni++) {
        mlo = fmaxf(mlo, fmaxf(sa[ni][0], sa[ni][1]));
        mhi = fmaxf(mhi, fmaxf(sa[ni][2], sa[ni][3]));
    }
    #pragma unroll
    for (int o = 1; o <= 2; o <<= 1) {
        mlo = fmaxf(mlo, __shfl_xor_sync(~0u, mlo, o));
        mhi = fmaxf(mhi, __shfl_xor_sync(~0u, mhi, o));
    }
    float slo = 0.f, shi = 0.f;
    #pragma unroll
    for (int ni = 0; ni < L/8; ni++) {
        float e0 = __expf((sa[ni][0] - mlo) * scale);
        float e1 = __expf((sa[ni][1] - mlo) * scale);
        float e2 = __expf((sa[ni][2] - mhi) * scale);
        float e3 = __expf((sa[ni][3] - mhi) * scale);
        sa[ni][0] = e0; sa[ni][1] = e1; sa[ni][2] = e2; sa[ni][3] = e3;
        slo += e0 + e1; shi += e2 + e3;
    }
    #pragma unroll
    for (int o = 1; o <= 2; o <<= 1) {
        slo += __shfl_xor_sync(~0u, slo, o);
        shi += __shfl_xor_sync(~0u, shi, o);
    }
    const float ilo = 1.f / slo, ihi = 1.f / shi;

    float oa[4][4];
    #pragma unroll
    for (int ni = 0; ni < 4; ni++)
        #pragma unroll
        for (int r = 0; r < 4; r++) oa[ni][r] = 0.f;

    {
        int vr7 = (lane & 7) + (((lane >> 3) & 1) << 3);
        int vu  = lane >> 4;
        #pragma unroll
        for (int s = 0; s < L/16; s++) {
            int row = s*16 + vr7;
            uint32_t rb = bv + (uint32_t)(row*128);
            int u1 = hh*4 + vu, u2 = hh*4 + vu + 2;
            uint32_t v0,v1,v2,v3,v4,v5,v6,v7;
            ldsm4t(v0, v1, v2, v3, rb + (uint32_t)((u1 ^ (row & 7)) << 4));
            ldsm4t(v4, v5, v6, v7, rb + (uint32_t)((u2 ^ (row & 7)) << 4));
            uint32_t a0 = pack2(sa[2*s  ][0], sa[2*s  ][1]);
            uint32_t a1 = pack2(sa[2*s  ][2], sa[2*s  ][3]);
            uint32_t a2 = pack2(sa[2*s+1][0], sa[2*s+1][1]);
            uint32_t a3 = pack2(sa[2*s+1][2], sa[2*s+1][3]);
            mma16816(oa[0], a0, a1, a2, a3, v0, v1);
            mma16816(oa[1], a0, a1, a2, a3, v2, v3);
            mma16816(oa[2], a0, a1, a2, a3, v4, v5);
            mma16816(oa[3], a0, a1, a2, a3, v6, v7);
        }
    }

    {
        int g2 = lane >> 2, t2 = (lane & 3) * 2;
        int h  = hp*2 + hh;
        int rlo = wi*16 + g2, rhi = rlo + 8;
        size_t glo = ((size_t)rlo * BtC + bt) * 256 + h*32 + t2;
        size_t ghi = ((size_t)rhi * BtC + bt) * 256 + h*32 + t2;
        #pragma unroll
        for (int ni = 0; ni < 4; ni++) {
            *(__half2*)&O[glo + ni*8] = __floats2half2_rn(oa[ni][0]*ilo, oa[ni][1]*ilo);
            *(__half2*)&O[ghi + ni*8] = __floats2half2_rn(oa[ni][2]*ihi, oa[ni][3]*ihi);
        }
    }
}

// ---------------------------------------------------------------------------
// Residual + scatter + LayerNorm1 (vectorized: lane owns 8 contiguous cols)
// ---------------------------------------------------------------------------
__global__ void __launch_bounds__(256)
resid_ln1(const float* __restrict__ src, const __half* __restrict__ mo,
          const float* __restrict__ g, const float* __restrict__ be,
          __half* __restrict__ out16)
{
    int tok  = blockIdx.x * 8 + (threadIdx.x >> 5);
    int lane = threadIdx.x & 31;
    int b = tok >> 13, n = tok & 8191;
    int h2 = n >> 9, bh2 = (n >> 6) & 7, ww2 = (n >> 3) & 7, w2 = n & 7;
    int ts = (h2*8 + ww2)*512 + b*64 + bh2*8 + w2;
    const float*  xs = src + (size_t)tok*256 + lane*8;
    const __half* ms = mo  + (size_t)ts *256 + lane*8;

    float4 x0 = *(const float4*)(xs);
    float4 x1 = *(const float4*)(xs + 4);
    uint2  m2 = *(const uint2*)(ms);
    uint2  m3 = *(const uint2*)(ms + 4);
    __half2 ma = *(__half2*)&m2.x, mb = *(__half2*)&m2.y;
    __half2 mc = *(__half2*)&m3.x, md = *(__half2*)&m3.y;
    float2 fa = __half22float2(ma), fb = __half22float2(mb);
    float2 fc = __half22float2(mc), fd = __half22float2(md);

    float v[8];
    v[0] = x0.x + fa.x; v[1] = x0.y + fa.y;
    v[2] = x0.z + fb.x; v[3] = x0.w + fb.y;
    v[4] = x1.x + fc.x; v[5] = x1.y + fc.y;
    v[6] = x1.z + fd.x; v[7] = x1.w + fd.y;

    float sum = 0.f, sq = 0.f;
    #pragma unroll
    for (int i = 0; i < 8; i++) { sum += v[i]; sq += v[i]*v[i]; }
    #pragma unroll
    for (int o = 16; o; o >>= 1) {
        sum += __shfl_xor_sync(~0u, sum, o);
        sq  += __shfl_xor_sync(~0u, sq , o);
    }
    float mu  = sum * (1.f/256.f);
    float var = sq * (1.f/256.f) - mu*mu;
    float inv = rsqrtf(var + 1e-5f);

    int c0 = lane*8;
    float4 g0 = *(const float4*)(g + c0);
    float4 g1 = *(const float4*)(g + c0 + 4);
    float4 e0 = *(const float4*)(be + c0);
    float4 e1 = *(const float4*)(be + c0 + 4);
    uint4 o4;
    o4.x = pack2((v[0]-mu)*inv*g0.x + e0.x, (v[1]-mu)*inv*g0.y + e0.y);
    o4.y = pack2((v[2]-mu)*inv*g0.z + e0.z, (v[3]-mu)*inv*g0.w + e0.w);
    o4.z = pack2((v[4]-mu)*inv*g1.x + e1.x, (v[5]-mu)*inv*g1.y + e1.y);
    o4.w = pack2((v[6]-mu)*inv*g1.z + e1.z, (v[7]-mu)*inv*g1.w + e1.w);
    *(uint4*)(out16 + (size_t)tok*256 + c0) = o4;
}

// ---------------------------------------------------------------------------
// Fused residual + LayerNorm2 + output transpose (vectorized fp16 inputs)
// ---------------------------------------------------------------------------
__global__ void __launch_bounds__(256)
add_ln_tr(const __half* __restrict__ a, const __half* __restrict__ bsrc,
          const float* __restrict__ g, const float* __restrict__ be,
          float* __restrict__ out)
{
    __shared__ float tile[32][257];
    int blk = blockIdx.x;
    int b = blk >> 8, nb = blk & 255;
    int n0 = nb * 32;
    int w = threadIdx.x >> 5, lane = threadIdx.x & 31;

    int c0 = lane*8;
    float4 gg0 = *(const float4*)(g + c0);
    float4 gg1 = *(const float4*)(g + c0 + 4);
    float4 ee0 = *(const float4*)(be + c0);
    float4 ee1 = *(const float4*)(be + c0 + 4);

    #pragma unroll
    for (int i = 0; i < 4; i++) {
        int lt = w*4 + i;
        size_t tok = (size_t)b*8192 + n0 + lt;
        const __half* xa = a    + tok*256 + c0;
        const __half* xb = bsrc + tok*256 + c0;
        uint4 ua = *(const uint4*)xa;
        uint4 ub = *(const uint4*)xb;
        const __half2* ha = (const __half2*)&ua;
        const __half2* hb = (const __half2*)&ub;
        float v[8];
        #pragma unroll
        for (int e = 0; e < 4; e++) {
            float2 pa = __half22float2(ha[e]);
            float2 pb = __half22float2(hb[e]);
            v[2*e]   = pa.x + pb.x;
            v[2*e+1] = pa.y + pb.y;
        }
        float sum = 0.f, sq = 0.f;
        #pragma unroll
        for (int e = 0; e < 8; e++) { sum += v[e]; sq += v[e]*v[e]; }
        #pragma unroll
        for (int o = 16; o; o >>= 1) {
            sum += __shfl_xor_sync(~0u, sum, o);
            sq  += __shfl_xor_sync(~0u, sq , o);
        }
        float mu  = sum * (1.f/256.f);
        float var = sq * (1.f/256.f) - mu*mu;
        float inv = rsqrtf(var + 1e-5f);
        tile[lt][c0+0] = (v[0]-mu)*inv*gg0.x + ee0.x;
        tile[lt][c0+1] = (v[1]-mu)*inv*gg0.y + ee0.y;
        tile[lt][c0+2] = (v[2]-mu)*inv*gg0.z + ee0.z;
        tile[lt][c0+3] = (v[3]-mu)*inv*gg0.w + ee0.w;
        tile[lt][c0+4] = (v[4]-mu)*inv*gg1.x + ee1.x;
        tile[lt][c0+5] = (v[5]-mu)*inv*gg1.y + ee1.y;
        tile[lt][c0+6] = (v[6]-mu)*inv*gg1.z + ee1.z;
        tile[lt][c0+7] = (v[7]-mu)*inv*gg1.w + ee1.w;
    }
    __syncthreads();

    size_t ob = (size_t)b*2097152 + n0 + lane;
    #pragma unroll
    for (int k = 0; k < 32; k++) {
        int c = w*32 + k;
        out[ob + (size_t)c*8192] = tile[lane][c];
    }
}

// ---------------------------------------------------------------------------
// Launch
// ---------------------------------------------------------------------------
extern "C" void kernel_launch(void* const* d_in, const int* in_sizes, int n_in,
                              void* d_out, int out_size)
{
    const float* src        = (const float*)d_in[0];
    const float* pos        = (const float*)d_in[1];
    const float* w_in_long  = (const float*)d_in[2];
    const float* b_in_long  = (const float*)d_in[3];
    const float* w_out_long = (const float*)d_in[4];
    const float* b_out_long = (const float*)d_in[5];
    const float* w_in_short = (const float*)d_in[6];
    const float* b_in_short = (const float*)d_in[7];
    const float* w_out_short= (const float*)d_in[8];
    const float* b_out_short= (const float*)d_in[9];
    const float* w1         = (const float*)d_in[10];
    const float* b1         = (const float*)d_in[11];
    const float* w2         = (const float*)d_in[12];
    const float* b2         = (const float*)d_in[13];
    const float* g1         = (const float*)d_in[14];
    const float* beta1      = (const float*)d_in[15];
    const float* g2         = (const float*)d_in[16];
    const float* beta2      = (const float*)d_in[17];
    float* out = (float*)d_out;

    static __half *p_xqk=nullptr,*p_xv,*p_q,*p_k,*p_v,*p_attn,*p_mo16,*p_x16,*p_h,*p_ff16;
    static __half *p_wl,*p_wol,*p_ws,*p_wos,*p_w1,*p_w2,*p_pos16;
    static bool init_done = false;
    if (!init_done) {
        cudaGetSymbolAddress((void**)&p_xqk , g_xqk );
        cudaGetSymbolAddress((void**)&p_xv  , g_xv  );
        cudaGetSymbolAddress((void**)&p_q   , g_q   );
        cudaGetSymbolAddress((void**)&p_k   , g_k   );
        cudaGetSymbolAddress((void**)&p_v   , g_v   );
        cudaGetSymbolAddress((void**)&p_attn, g_attn);
        cudaGetSymbolAddress((void**)&p_mo16, g_mo16);
        cudaGetSymbolAddress((void**)&p_x16 , g_x16 );
        cudaGetSymbolAddress((void**)&p_ff16, g_ff16);
        cudaGetSymbolAddress((void**)&p_h   , g_h   );
        cudaGetSymbolAddress((void**)&p_wl  , g_wl  );
        cudaGetSymbolAddress((void**)&p_wol , g_wol );
        cudaGetSymbolAddress((void**)&p_ws  , g_ws  );
        cudaGetSymbolAddress((void**)&p_wos , g_wos );
        cudaGetSymbolAddress((void**)&p_w1  , g_w1h );
        cudaGetSymbolAddress((void**)&p_w2  , g_w2h );
        cudaGetSymbolAddress((void**)&p_pos16, g_pos16);
        cudaFuncSetAttribute((const void*)gemm_h<0,1,4>,
            cudaFuncAttributeMaxDynamicSharedMemorySize, GEMMH_SMEM);
        cudaFuncSetAttribute((const void*)gemm_h<0,1,16>,
            cudaFuncAttributeMaxDynamicSharedMemorySize, GEMMH_SMEM);
        cudaFuncSetAttribute((const void*)gemm_h<1,1,4>,
            cudaFuncAttributeMaxDynamicSharedMemorySize, GEMMH_SMEM);
        cudaFuncSetAttribute((const void*)gemm_h<2,1,4>,
            cudaFuncAttributeMaxDynamicSharedMemorySize, GEMMH_SMEM);
        cudaFuncSetAttribute((const void*)gemm_h<3,1,4>,
            cudaFuncAttributeMaxDynamicSharedMemorySize, GEMMH_SMEM);
        init_done = true;
    }

    // ---- fused prep: weight/pos fp16 conversion + long gather ----
    prep_all<<<3072 + TOK/4, 256>>>(w_in_long, w_out_long, w_in_short, w_out_short,
                                    w1, w2, pos, src, p_xqk, p_xv);

    const dim3 gQKV(TOK/128, 6);
    const dim3 g256(TOK/128, 2);
    const dim3 gHID(TOK/128, 8);

    // ---- long-range MHA ----
    gemm_h<2,1,4><<<gQKV, 256, GEMMH_SMEM>>>(p_xqk, p_xv, p_wl, b_in_long, nullptr,
                                             p_q, p_k, p_v, 768);
    attn_tc2<64><<<1024*4, 256>>>(p_q, p_k, p_v, p_attn, 1024);
    // out-proj long with fused short-gather scatter (fp16 pos)
    gemm_h<3,1,4><<<g256, 256, GEMMH_SMEM>>>(p_attn, nullptr, p_wol, b_out_long, p_pos16,
                                             p_xqk, p_xv, nullptr, 256);

    // ---- short-range MHA ----
    gemm_h<2,1,4><<<gQKV, 256, GEMMH_SMEM>>>(p_xqk, p_xv, p_ws, b_in_short, nullptr,
                                             p_q, p_k, p_v, 768);
    attn_tc2<128><<<512*4, 512>>>(p_q, p_k, p_v, p_attn, 512);
    gemm_h<0,1,4><<<g256, 256, GEMMH_SMEM>>>(p_attn, nullptr, p_wos, b_out_short, nullptr,
                                             p_mo16, nullptr, nullptr, 256);

    // ---- residual + LN1 (fp16 output only) ----
    resid_ln1<<<TOK/8, 256>>>(src, p_mo16, g1, beta1, p_x16);

    // ---- FFN ----
    gemm_h<1,1,4><<<gHID, 256, GEMMH_SMEM>>>(p_x16, nullptr, p_w1, b1, nullptr,
                                             p_h, nullptr, nullptr, 1024);
    gemm_h<0,1,16><<<g256, 256, GEMMH_SMEM>>>(p_h, nullptr, p_w2, b2, nullptr,
                                              p_ff16, nullptr, nullptr, 256);

    // ---- residual + LN2 + output transpose (fused, fp16 inputs) ----
    add_ln_tr<<<2048, 256>>>(p_x16, p_ff16, g2, beta2, out);
}

// round 17
// speedup vs baseline: 1.0979x; 1.0151x over previous
#include <cuda_runtime.h>
#include <cuda_fp16.h>
#include <cstdint>

#define TOK    65536
#define CDIM   256
#define HID    1024

// ---------------------------------------------------------------------------
// Scratch
// ---------------------------------------------------------------------------
__device__ __half g_xqk [TOK*CDIM];
__device__ __half g_xv  [TOK*CDIM];
__device__ __half g_q   [TOK*CDIM];
__device__ __half g_k   [TOK*CDIM];
__device__ __half g_v   [TOK*CDIM];
__device__ __half g_attn[TOK*CDIM];
__device__ __half g_mo16[TOK*CDIM];
__device__ __half g_x16 [TOK*CDIM];
__device__ __half g_h   [TOK*HID];
__device__ __half g_ff16[TOK*CDIM];
// fp16 weights + pos
__device__ __half g_wl [768*256];
__device__ __half g_wol[256*256];
__device__ __half g_ws [768*256];
__device__ __half g_wos[256*256];
__device__ __half g_w1h[HID*256];
__device__ __half g_w2h[256*HID];
__device__ __half g_pos16[8192*256];

// ---------------------------------------------------------------------------
// PTX helpers
// ---------------------------------------------------------------------------
__device__ __forceinline__ void cpasync16(uint32_t dst, const void* src) {
    asm volatile("cp.async.cg.shared.global [%0], [%1], 16;\n" :: "r"(dst), "l"(src));
}
__device__ __forceinline__ void cp_commit() {
    asm volatile("cp.async.commit_group;\n");
}
template<int N>
__device__ __forceinline__ void cp_wait() {
    asm volatile("cp.async.wait_group %0;\n" :: "n"(N));
}
__device__ __forceinline__ void ldsm4(uint32_t& r0, uint32_t& r1,
                                      uint32_t& r2, uint32_t& r3, uint32_t addr) {
    asm volatile("ldmatrix.sync.aligned.m8n8.x4.shared.b16 {%0,%1,%2,%3}, [%4];"
                 : "=r"(r0), "=r"(r1), "=r"(r2), "=r"(r3) : "r"(addr));
}
__device__ __forceinline__ void ldsm4t(uint32_t& r0, uint32_t& r1,
                                       uint32_t& r2, uint32_t& r3, uint32_t addr) {
    asm volatile("ldmatrix.sync.aligned.m8n8.x4.trans.shared.b16 {%0,%1,%2,%3}, [%4];"
                 : "=r"(r0), "=r"(r1), "=r"(r2), "=r"(r3) : "r"(addr));
}
__device__ __forceinline__ void mma16816(float c[4],
    uint32_t a0, uint32_t a1, uint32_t a2, uint32_t a3, uint32_t b0, uint32_t b1)
{
    asm volatile(
        "mma.sync.aligned.m16n8k16.row.col.f32.f16.f16.f32 "
        "{%0,%1,%2,%3}, {%4,%5,%6,%7}, {%8,%9}, {%0,%1,%2,%3};"
        : "+f"(c[0]), "+f"(c[1]), "+f"(c[2]), "+f"(c[3])
        : "r"(a0), "r"(a1), "r"(a2), "r"(a3), "r"(b0), "r"(b1));
}
__device__ __forceinline__ uint32_t pack2(float a, float b) {
    __half2 h = __floats2half2_rn(a, b);
    return *(uint32_t*)&h;
}

// short-layout permutation: long-flat token f -> (short token ts, pos index n)
__device__ __forceinline__ void fmap_short(int f, int& ts, int& n) {
    int b2 = f >> 13, bh2 = (f >> 10) & 7, h2 = (f >> 6) & 15;
    int w2 = (f >> 3) & 7, ww2 = f & 7;
    ts = (h2*8 + ww2)*512 + b2*64 + bh2*8 + w2;
    int Lf = f >> 10, r = f & 1023;
    int bh = Lf >> 3, w = Lf & 7, hh = (r >> 3) & 15, ww = r & 7;
    n = bh*1024 + hh*64 + w*8 + ww;
}

// ---------------------------------------------------------------------------
// FP16 tensor-core GEMM (128x128, 2 CTAs/SM, 3-stage, 1 barrier/chunk)
// KT templated. PDL: 1 = prefetch B (weights, >=2 kernels old) before
// cudaGridDependencySynchronize; 0 = sync before all loads (B from immediate
// predecessor, e.g. QKV-long whose weights come from prep).
// EPI: 0 plain, 1 ReLU, 2 fused-QKV split, 3 fused short-gather scatter
// ---------------------------------------------------------------------------
#define STAGE_B 32768
#define GEMMH_SMEM (3*STAGE_B)

__device__ __forceinline__ void load_half16(const __half* __restrict__ P, int base,
                                            int K, int kt, uint32_t sbase, int tid)
{
    #pragma unroll
    for (int j = 0; j < 4; j++) {
        int idx = tid*4 + j;
        int row = idx >> 3, c = idx & 7;
        uint32_t off = (uint32_t)(row*128 + ((c ^ (row & 7)) << 4));
        cpasync16(sbase + off, P + (size_t)(base + row)*K + kt*64 + c*8);
    }
    cp_commit();
}

__device__ __forceinline__ void load_chunk16(const __half* __restrict__ A,
                                             const __half* __restrict__ B,
                                             int bm, int bn, int K, int kt,
                                             uint32_t sbase, int tid)
{
    #pragma unroll
    for (int j = 0; j < 4; j++) {
        int idx = tid*4 + j;
        int row = idx >> 3, c = idx & 7;
        uint32_t off = (uint32_t)(row*128 + ((c ^ (row & 7)) << 4));
        cpasync16(sbase + off, A + (size_t)(bm + row)*K + kt*64 + c*8);
    }
    #pragma unroll
    for (int j = 0; j < 4; j++) {
        int idx = tid*4 + j;
        int row = idx >> 3, c = idx & 7;
        uint32_t off = (uint32_t)(row*128 + ((c ^ (row & 7)) << 4));
        cpasync16(sbase + 16384 + off, B + (size_t)(bn + row)*K + kt*64 + c*8);
    }
    cp_commit();
}

template<int EPI, int KT, int PDL>
__global__ void __launch_bounds__(256, 2)
gemm_h(const __half* __restrict__ A0, const __half* __restrict__ A1,
       const __half* __restrict__ B,  const float* __restrict__ bias,
       const __half* __restrict__ pos16,
       void* C0, void* C1, void* C2, int N)
{
    constexpr int K = KT * 64;
    extern __shared__ __align__(128) char dsm[];
    const int tid = threadIdx.x;
    const int bm  = blockIdx.x * 128;
    const int bnG = blockIdx.y * 128;

    const __half* A = A0;
    if (EPI == 2) A = (blockIdx.y < 4) ? A0 : A1;

    uint32_t sb = (uint32_t)__cvta_generic_to_shared(dsm);

    const int lane = tid & 31, wid = tid >> 5;
    const int wm = (wid >> 2) * 64;
    const int wn = (wid & 3) * 32;
    const int lq = lane >> 3;
    const int l7 = lane & 7;

    float acc[4][4][4];
    #pragma unroll
    for (int mi = 0; mi < 4; mi++)
        #pragma unroll
        for (int ni = 0; ni < 4; ni++)
            #pragma unroll
            for (int r = 0; r < 4; r++) acc[mi][ni][r] = 0.f;

    if (PDL == 1) {
        // B (weights) is safe pre-sync: written >=2 kernels back.
        load_half16(B, bnG, K, 0, sb + 16384,           tid);   // group: B0
        load_half16(B, bnG, K, 1, sb + STAGE_B + 16384, tid);   // group: B1
        cudaGridDependencySynchronize();
        load_half16(A, bm, K, 0, sb,           tid);            // group: A0
        load_half16(A, bm, K, 1, sb + STAGE_B, tid);            // group: A1
    } else {
        cudaGridDependencySynchronize();
        load_chunk16(A, B, bm, bnG, K, 0, sb,           tid);
        load_chunk16(A, B, bm, bnG, K, 1, sb + STAGE_B, tid);
    }

    int arow[4], brow[2];
    #pragma unroll
    for (int mi = 0; mi < 4; mi++) arow[mi] = wm + mi*16 + (lq & 1)*8 + l7;
    #pragma unroll
    for (int p = 0; p < 2; p++)    brow[p]  = wn + p*16 + (lq >> 1)*8 + l7;
    const int aqh = lq >> 1;
    const int bqh = lq & 1;

    #pragma unroll
    for (int kt = 0; kt < KT; kt++) {
        // PDL=1 pending groups at kt=0: {B0,B1,A0,A1}; wait<1> completes
        // B0,B1,A0 (chunk0 ready). kt=1: {A1,C2} -> A1 done. Same semantics
        // as the combined-group ladder.
        if (kt + 2 < KT) cp_wait<1>(); else cp_wait<0>();
        __syncthreads();
        if (kt + 2 < KT)
            load_chunk16(A, B, bm, bnG, K, kt + 2,
                         sb + (uint32_t)((kt + 2) % 3)*STAGE_B, tid);

        uint32_t Ab = sb + (uint32_t)(kt % 3)*STAGE_B;
        uint32_t Bb = Ab + 16384;

        #pragma unroll
        for (int s = 0; s < 4; s++) {
            uint32_t af[4][4];
            #pragma unroll
            for (int mi = 0; mi < 4; mi++) {
                int row = arow[mi];
                uint32_t addr = Ab + (uint32_t)(row*128 +
                                (((2*s + aqh) ^ (row & 7)) << 4));
                ldsm4(af[mi][0], af[mi][1], af[mi][2], af[mi][3], addr);
            }
            uint32_t bf[4][2];
            #pragma unroll
            for (int p = 0; p < 2; p++) {
                int row = brow[p];
                uint32_t addr = Bb + (uint32_t)(row*128 +
                                (((2*s + bqh) ^ (row & 7)) << 4));
                ldsm4(bf[2*p][0], bf[2*p][1], bf[2*p+1][0], bf[2*p+1][1], addr);
            }
            #pragma unroll
            for (int mi = 0; mi < 4; mi++)
                #pragma unroll
                for (int ni = 0; ni < 4; ni++)
                    mma16816(acc[mi][ni], af[mi][0], af[mi][1], af[mi][2], af[mi][3],
                             bf[ni][0], bf[ni][1]);
        }
    }

    // all dependent global reads consumed -> release dependent launch
    cudaTriggerProgrammaticLaunchCompletion();

    const int g2 = lane >> 2, t2 = lane & 3;

    if (EPI == 3) {
        __half* xqk = (__half*)C0;
        __half* xv  = (__half*)C1;
        #pragma unroll
        for (int mi = 0; mi < 4; mi++) {
            int f0 = bm + wm + mi*16 + g2;
            int f1 = f0 + 8;
            int ts0, n0, ts1, n1;
            fmap_short(f0, ts0, n0);
            fmap_short(f1, ts1, n1);
            #pragma unroll
            for (int ni = 0; ni < 4; ni++) {
                int cg = bnG + wn + ni*8 + t2*2;
                float b0 = bias[cg], b1 = bias[cg + 1];
                float v0 = acc[mi][ni][0] + b0;
                float v1 = acc[mi][ni][1] + b1;
                float v2 = acc[mi][ni][2] + b0;
                float v3 = acc[mi][ni][3] + b1;
                float2 p0 = __half22float2(*(const __half2*)&pos16[(size_t)n0*256 + cg]);
                float2 p1 = __half22float2(*(const __half2*)&pos16[(size_t)n1*256 + cg]);
                *(__half2*)&xv [(size_t)ts0*256 + cg] = __floats2half2_rn(v0, v1);
                *(__half2*)&xv [(size_t)ts1*256 + cg] = __floats2half2_rn(v2, v3);
                *(__half2*)&xqk[(size_t)ts0*256 + cg] = __floats2half2_rn(v0+p0.x, v1+p0.y);
                *(__half2*)&xqk[(size_t)ts1*256 + cg] = __floats2half2_rn(v2+p1.x, v3+p1.y);
            }
        }
        return;
    }

    void* dstp = C0;
    int ldc = N, colbase = bnG;
    if (EPI == 2) {
        int region = blockIdx.y >> 1;
        dstp = (region == 0) ? C0 : (region == 1 ? C1 : C2);
        ldc = 256;
        colbase = (blockIdx.y & 1) * 128;
    }

    #pragma unroll
    for (int mi = 0; mi < 4; mi++) {
        #pragma unroll
        for (int ni = 0; ni < 4; ni++) {
            int row = bm + wm + mi*16 + g2;
            int cg  = bnG + wn + ni*8 + t2*2;
            int cl  = colbase + wn + ni*8 + t2*2;
            float b0 = bias[cg], b1 = bias[cg + 1];
            float v0 = acc[mi][ni][0] + b0;
            float v1 = acc[mi][ni][1] + b1;
            float v2 = acc[mi][ni][2] + b0;
            float v3 = acc[mi][ni][3] + b1;
            if (EPI == 1) {
                v0 = fmaxf(v0, 0.f); v1 = fmaxf(v1, 0.f);
                v2 = fmaxf(v2, 0.f); v3 = fmaxf(v3, 0.f);
            }
            __half* d = (__half*)dstp;
            *(__half2*)&d[(size_t)row      *ldc + cl] = __floats2half2_rn(v0, v1);
            *(__half2*)&d[(size_t)(row + 8)*ldc + cl] = __floats2half2_rn(v2, v3);
        }
    }
}

// ---------------------------------------------------------------------------
// Merged prep kernel (first in chain; trigger early so QKV-long can set up)
// ---------------------------------------------------------------------------
__global__ void __launch_bounds__(256)
prep_all(const float* __restrict__ wl, const float* __restrict__ wol,
         const float* __restrict__ ws, const float* __restrict__ wos,
         const float* __restrict__ w1, const float* __restrict__ w2,
         const float* __restrict__ pos, const float* __restrict__ src,
         __half* __restrict__ xqk, __half* __restrict__ xv)
{
    cudaTriggerProgrammaticLaunchCompletion();
    int blk = blockIdx.x;
    if (blk < 3072) {
        const float* s; __half* d;
        if      (blk < 192)  { s = wl;  d = g_wl;               }
        else if (blk < 256)  { s = wol; d = g_wol; blk -= 192;  }
        else if (blk < 448)  { s = ws;  d = g_ws;  blk -= 256;  }
        else if (blk < 512)  { s = wos; d = g_wos; blk -= 448;  }
        else if (blk < 768)  { s = w1;  d = g_w1h; blk -= 512;  }
        else if (blk < 1024) { s = w2;  d = g_w2h; blk -= 768;  }
        else                 { s = pos; d = g_pos16; blk -= 1024; }
        int i = (blk*256 + threadIdx.x) * 4;
        float4 v = *(const float4*)(s + i);
        uint2 o; o.x = pack2(v.x, v.y); o.y = pack2(v.z, v.w);
        *(uint2*)(d + i) = o;
        return;
    }
    blk -= 3072;
    int t  = blk * 4 + (threadIdx.x >> 6);
    int c4 = (threadIdx.x & 63) * 4;
    int Lc = t >> 10, Bt = t & 1023;
    int bh = Lc >> 3, w = Lc & 7;
    int b  = Bt >> 7, hh = (Bt >> 3) & 15, ww = Bt & 7;
    int n  = bh*1024 + hh*64 + w*8 + ww;
    float4 s4 = *(const float4*)(src + ((size_t)b*8192 + n)*256 + c4);
    float4 p4 = *(const float4*)(pos + (size_t)n*256 + c4);
    uint2 ov; ov.x = pack2(s4.x, s4.y); ov.y = pack2(s4.z, s4.w);
    *(uint2*)(xv + (size_t)t*256 + c4) = ov;
    uint2 oq; oq.x = pack2(s4.x+p4.x, s4.y+p4.y); oq.y = pack2(s4.z+p4.z, s4.w+p4.w);
    *(uint2*)(xqk + (size_t)t*256 + c4) = oq;
}

// ---------------------------------------------------------------------------
// Tensor-core attention, two heads per CTA (R8-proven) + PDL
// ---------------------------------------------------------------------------
template<int L>
__global__ void __launch_bounds__(4*L)
attn_tc2(const __half* __restrict__ Q, const __half* __restrict__ K,
         const __half* __restrict__ V, __half* __restrict__ O, int BtC)
{
    constexpr int WPH = L/16;
    __shared__ __align__(128) __half sQ[L*64];
    __shared__ __align__(128) __half sK[L*64];
    __shared__ __align__(128) __half sV[L*64];

    const int bt   = blockIdx.x % BtC;
    const int hp   = blockIdx.x / BtC;
    const int tid  = threadIdx.x;
    const int lane = tid & 31, w = tid >> 5;
    const int hh   = w / WPH;
    const int wi   = w % WPH;
    const float scale = 0.17677669529663687f;

    uint32_t bq = (uint32_t)__cvta_generic_to_shared(sQ);
    uint32_t bk = (uint32_t)__cvta_generic_to_shared(sK);
    uint32_t bv = (uint32_t)__cvta_generic_to_shared(sV);

    cudaGridDependencySynchronize();

    #pragma unroll
    for (int seg = tid; seg < L*8; seg += 4*L) {
        int l = seg >> 3, u = seg & 7;
        size_t g = ((size_t)l * BtC + bt) * 256 + hp*64 + u*8;
        uint32_t so = (uint32_t)(l*128 + ((u ^ (l & 7)) << 4));
        cpasync16(bq + so, Q + g);
        cpasync16(bk + so, K + g);
        cpasync16(bv + so, V + g);
    }
    cp_commit();
    cp_wait<0>();
    __syncthreads();

    cudaTriggerProgrammaticLaunchCompletion();

    float sa[L/8][4];
    #pragma unroll
    for (int ni = 0; ni < L/8; ni++)
        #pragma unroll
        for (int r = 0; r < 4; r++) sa[ni][r] = 0.f;

    uint32_t a[2][4];
    {
        int arow = wi*16 + (lane & 15);
        uint32_t ab = bq + (uint32_t)(arow*128);
        #pragma unroll
        for (int s = 0; s < 2; s++) {
            int unit = hh*4 + 2*s + (lane >> 4);
            ldsm4(a[s][0], a[s][1], a[s][2], a[s][3],
                  ab + (uint32_t)((unit ^ (arow & 7)) << 4));
        }
    }
    {
        int br7 = (lane & 7) + ((lane >> 4) << 3);
        int bu  = (lane >> 3) & 1;
        #pragma unroll
        for (int j = 0; j < L/16; j++) {
            int row = j*16 + br7;
            uint32_t rb = bk + (uint32_t)(row*128);
            #pragma unroll
            for (int s = 0; s < 2; s++) {
                int unit = hh*4 + 2*s + bu;
                uint32_t b0, b1, b2, b3;
                ldsm4(b0, b1, b2, b3, rb + (uint32_t)((unit ^ (row & 7)) << 4));
                mma16816(sa[2*j],   a[s][0], a[s][1], a[s][2], a[s][3], b0, b1);
                mma16816(sa[2*j+1], a[s][0], a[s][1], a[s][2], a[s][3], b2, b3);
            }
        }
    }

    float mlo = -1e30f, mhi = -1e30f;
    #pragma unroll
    for (int ni = 0; ni < L/8; ni++) {
        mlo = fmaxf(mlo, fmaxf(sa[ni][0], sa[ni][1]));
        mhi = fmaxf(mhi, fmaxf(sa[ni][2], sa[ni][3]));
    }
    #pragma unroll
    for (int o = 1; o <= 2; o <<= 1) {
        mlo = fmaxf(mlo, __shfl_xor_sync(~0u, mlo, o));
        mhi = fmaxf(mhi, __shfl_xor_sync(~0u, mhi, o));
    }
    float slo = 0.f, shi = 0.f;
    #pragma unroll
    for (int ni = 0; ni < L/8; ni++) {
        float e0 = __expf((sa[ni][0] - mlo) * scale);
        float e1 = __expf((sa[ni][1] - mlo) * scale);
        float e2 = __expf((sa[ni][2] - mhi) * scale);
        float e3 = __expf((sa[ni][3] - mhi) * scale);
        sa[ni][0] = e0; sa[ni][1] = e1; sa[ni][2] = e2; sa[ni][3] = e3;
        slo += e0 + e1; shi += e2 + e3;
    }
    #pragma unroll
    for (int o = 1; o <= 2; o <<= 1) {
        slo += __shfl_xor_sync(~0u, slo, o);
        shi += __shfl_xor_sync(~0u, shi, o);
    }
    const float ilo = 1.f / slo, ihi = 1.f / shi;

    float oa[4][4];
    #pragma unroll
    for (int ni = 0; ni < 4; ni++)
        #pragma unroll
        for (int r = 0; r < 4; r++) oa[ni][r] = 0.f;

    {
        int vr7 = (lane & 7) + (((lane >> 3) & 1) << 3);
        int vu  = lane >> 4;
        #pragma unroll
        for (int s = 0; s < L/16; s++) {
            int row = s*16 + vr7;
            uint32_t rb = bv + (uint32_t)(row*128);
            int u1 = hh*4 + vu, u2 = hh*4 + vu + 2;
            uint32_t v0,v1,v2,v3,v4,v5,v6,v7;
            ldsm4t(v0, v1, v2, v3, rb + (uint32_t)((u1 ^ (row & 7)) << 4));
            ldsm4t(v4, v5, v6, v7, rb + (uint32_t)((u2 ^ (row & 7)) << 4));
            uint32_t a0 = pack2(sa[2*s  ][0], sa[2*s  ][1]);
            uint32_t a1 = pack2(sa[2*s  ][2], sa[2*s  ][3]);
            uint32_t a2 = pack2(sa[2*s+1][0], sa[2*s+1][1]);
            uint32_t a3 = pack2(sa[2*s+1][2], sa[2*s+1][3]);
            mma16816(oa[0], a0, a1, a2, a3, v0, v1);
            mma16816(oa[1], a0, a1, a2, a3, v2, v3);
            mma16816(oa[2], a0, a1, a2, a3, v4, v5);
            mma16816(oa[3], a0, a1, a2, a3, v6, v7);
        }
    }

    {
        int g2 = lane >> 2, t2 = (lane & 3) * 2;
        int h  = hp*2 + hh;
        int rlo = wi*16 + g2, rhi = rlo + 8;
        size_t glo = ((size_t)rlo * BtC + bt) * 256 + h*32 + t2;
        size_t ghi = ((size_t)rhi * BtC + bt) * 256 + h*32 + t2;
        #pragma unroll
        for (int ni = 0; ni < 4; ni++) {
            *(__half2*)&O[glo + ni*8] = __floats2half2_rn(oa[ni][0]*ilo, oa[ni][1]*ilo);
            *(__half2*)&O[ghi + ni*8] = __floats2half2_rn(oa[ni][2]*ihi, oa[ni][3]*ihi);
        }
    }
}

// ---------------------------------------------------------------------------
// Residual + scatter + LayerNorm1 (vectorized) + PDL
// ---------------------------------------------------------------------------
__global__ void __launch_bounds__(256)
resid_ln1(const float* __restrict__ src, const __half* __restrict__ mo,
          const float* __restrict__ g, const float* __restrict__ be,
          __half* __restrict__ out16)
{
    int tok  = blockIdx.x * 8 + (threadIdx.x >> 5);
    int lane = threadIdx.x & 31;
    int b = tok >> 13, n = tok & 8191;
    int h2 = n >> 9, bh2 = (n >> 6) & 7, ww2 = (n >> 3) & 7, w2 = n & 7;
    int ts = (h2*8 + ww2)*512 + b*64 + bh2*8 + w2;
    const float*  xs = src + (size_t)tok*256 + lane*8;
    const __half* ms = mo  + (size_t)ts *256 + lane*8;

    cudaGridDependencySynchronize();

    float4 x0 = *(const float4*)(xs);
    float4 x1 = *(const float4*)(xs + 4);
    uint2  m2 = *(const uint2*)(ms);
    uint2  m3 = *(const uint2*)(ms + 4);
    __half2 ma = *(__half2*)&m2.x, mb = *(__half2*)&m2.y;
    __half2 mc = *(__half2*)&m3.x, md = *(__half2*)&m3.y;
    float2 fa = __half22float2(ma), fb = __half22float2(mb);
    float2 fc = __half22float2(mc), fd = __half22float2(md);

    float v[8];
    v[0] = x0.x + fa.x; v[1] = x0.y + fa.y;
    v[2] = x0.z + fb.x; v[3] = x0.w + fb.y;
    v[4] = x1.x + fc.x; v[5] = x1.y + fc.y;
    v[6] = x1.z + fd.x; v[7] = x1.w + fd.y;

    cudaTriggerProgrammaticLaunchCompletion();

    float sum = 0.f, sq = 0.f;
    #pragma unroll
    for (int i = 0; i < 8; i++) { sum += v[i]; sq += v[i]*v[i]; }
    #pragma unroll
    for (int o = 16; o; o >>= 1) {
        sum += __shfl_xor_sync(~0u, sum, o);
        sq  += __shfl_xor_sync(~0u, sq , o);
    }
    float mu  = sum * (1.f/256.f);
    float var = sq * (1.f/256.f) - mu*mu;
    float inv = rsqrtf(var + 1e-5f);

    int c0 = lane*8;
    float4 g0 = *(const float4*)(g + c0);
    float4 g1 = *(const float4*)(g + c0 + 4);
    float4 e0 = *(const float4*)(be + c0);
    float4 e1 = *(const float4*)(be + c0 + 4);
    uint4 o4;
    o4.x = pack2((v[0]-mu)*inv*g0.x + e0.x, (v[1]-mu)*inv*g0.y + e0.y);
    o4.y = pack2((v[2]-mu)*inv*g0.z + e0.z, (v[3]-mu)*inv*g0.w + e0.w);
    o4.z = pack2((v[4]-mu)*inv*g1.x + e1.x, (v[5]-mu)*inv*g1.y + e1.y);
    o4.w = pack2((v[6]-mu)*inv*g1.z + e1.z, (v[7]-mu)*inv*g1.w + e1.w);
    *(uint4*)(out16 + (size_t)tok*256 + c0) = o4;
}

// ---------------------------------------------------------------------------
// Fused residual + LayerNorm2 + output transpose (vectorized) + PDL
// ---------------------------------------------------------------------------
__global__ void __launch_bounds__(256)
add_ln_tr(const __half* __restrict__ a, const __half* __restrict__ bsrc,
          const float* __restrict__ g, const float* __restrict__ be,
          float* __restrict__ out)
{
    __shared__ float tile[32][257];
    int blk = blockIdx.x;
    int b = blk >> 8, nb = blk & 255;
    int n0 = nb * 32;
    int w = threadIdx.x >> 5, lane = threadIdx.x & 31;

    int c0 = lane*8;
    float4 gg0 = *(const float4*)(g + c0);
    float4 gg1 = *(const float4*)(g + c0 + 4);
    float4 ee0 = *(const float4*)(be + c0);
    float4 ee1 = *(const float4*)(be + c0 + 4);

    cudaGridDependencySynchronize();

    #pragma unroll
    for (int i = 0; i < 4; i++) {
        int lt = w*4 + i;
        size_t tok = (size_t)b*8192 + n0 + lt;
        const __half* xa = a    + tok*256 + c0;
        const __half* xb = bsrc + tok*256 + c0;
        uint4 ua = *(const uint4*)xa;
        uint4 ub = *(const uint4*)xb;
        const __half2* ha = (const __half2*)&ua;
        const __half2* hb = (const __half2*)&ub;
        float v[8];
        #pragma unroll
        for (int e = 0; e < 4; e++) {
            float2 pa = __half22float2(ha[e]);
            float2 pb = __half22float2(hb[e]);
            v[2*e]   = pa.x + pb.x;
            v[2*e+1] = pa.y + pb.y;
        }
        float sum = 0.f, sq = 0.f;
        #pragma unroll
        for (int e = 0; e < 8; e++) { sum += v[e]; sq += v[e]*v[e]; }
        #pragma unroll
        for (int o = 16; o; o >>= 1) {
            sum += __shfl_xor_sync(~0u, sum, o);
            sq  += __shfl_xor_sync(~0u, sq , o);
        }
        float mu  = sum * (1.f/256.f);
        float var = sq * (1.f/256.f) - mu*mu;
        float inv = rsqrtf(var + 1e-5f);
        tile[lt][c0+0] = (v[0]-mu)*inv*gg0.x + ee0.x;
        tile[lt][c0+1] = (v[1]-mu)*inv*gg0.y + ee0.y;
        tile[lt][c0+2] = (v[2]-mu)*inv*gg0.z + ee0.z;
        tile[lt][c0+3] = (v[3]-mu)*inv*gg0.w + ee0.w;
        tile[lt][c0+4] = (v[4]-mu)*inv*gg1.x + ee1.x;
        tile[lt][c0+5] = (v[5]-mu)*inv*gg1.y + ee1.y;
        tile[lt][c0+6] = (v[6]-mu)*inv*gg1.z + ee1.z;
        tile[lt][c0+7] = (v[7]-mu)*inv*gg1.w + ee1.w;
    }
    __syncthreads();

    size_t ob = (size_t)b*2097152 + n0 + lane;
    #pragma unroll
    for (int k = 0; k < 32; k++) {
        int c = w*32 + k;
        out[ob + (size_t)c*8192] = tile[lane][c];
    }
}

// ---------------------------------------------------------------------------
// PDL launch helper
// ---------------------------------------------------------------------------
template<typename Kern, typename... Args>
static inline void launch_pdl(Kern k, dim3 grid, dim3 block, size_t smem,
                              Args... args)
{
    cudaLaunchConfig_t cfg = {};
    cfg.gridDim = grid;
    cfg.blockDim = block;
    cfg.dynamicSmemBytes = smem;
    cfg.stream = 0;
    cudaLaunchAttribute at[1];
    at[0].id = cudaLaunchAttributeProgrammaticStreamSerialization;
    at[0].val.programmaticStreamSerializationAllowed = 1;
    cfg.attrs = at;
    cfg.numAttrs = 1;
    cudaLaunchKernelEx(&cfg, k, args...);
}

// ---------------------------------------------------------------------------
// Launch
// ---------------------------------------------------------------------------
extern "C" void kernel_launch(void* const* d_in, const int* in_sizes, int n_in,
                              void* d_out, int out_size)
{
    const float* src        = (const float*)d_in[0];
    const float* pos        = (const float*)d_in[1];
    const float* w_in_long  = (const float*)d_in[2];
    const float* b_in_long  = (const float*)d_in[3];
    const float* w_out_long = (const float*)d_in[4];
    const float* b_out_long = (const float*)d_in[5];
    const float* w_in_short = (const float*)d_in[6];
    const float* b_in_short = (const float*)d_in[7];
    const float* w_out_short= (const float*)d_in[8];
    const float* b_out_short= (const float*)d_in[9];
    const float* w1         = (const float*)d_in[10];
    const float* b1         = (const float*)d_in[11];
    const float* w2         = (const float*)d_in[12];
    const float* b2         = (const float*)d_in[13];
    const float* g1         = (const float*)d_in[14];
    const float* beta1      = (const float*)d_in[15];
    const float* g2         = (const float*)d_in[16];
    const float* beta2      = (const float*)d_in[17];
    float* out = (float*)d_out;

    static __half *p_xqk=nullptr,*p_xv,*p_q,*p_k,*p_v,*p_attn,*p_mo16,*p_x16,*p_h,*p_ff16;
    static __half *p_wl,*p_wol,*p_ws,*p_wos,*p_w1,*p_w2,*p_pos16;
    static bool init_done = false;
    if (!init_done) {
        cudaGetSymbolAddress((void**)&p_xqk , g_xqk );
        cudaGetSymbolAddress((void**)&p_xv  , g_xv  );
        cudaGetSymbolAddress((void**)&p_q   , g_q   );
        cudaGetSymbolAddress((void**)&p_k   , g_k   );
        cudaGetSymbolAddress((void**)&p_v   , g_v   );
        cudaGetSymbolAddress((void**)&p_attn, g_attn);
        cudaGetSymbolAddress((void**)&p_mo16, g_mo16);
        cudaGetSymbolAddress((void**)&p_x16 , g_x16 );
        cudaGetSymbolAddress((void**)&p_ff16, g_ff16);
        cudaGetSymbolAddress((void**)&p_h   , g_h   );
        cudaGetSymbolAddress((void**)&p_wl  , g_wl  );
        cudaGetSymbolAddress((void**)&p_wol , g_wol );
        cudaGetSymbolAddress((void**)&p_ws  , g_ws  );
        cudaGetSymbolAddress((void**)&p_wos , g_wos );
        cudaGetSymbolAddress((void**)&p_w1  , g_w1h );
        cudaGetSymbolAddress((void**)&p_w2  , g_w2h );
        cudaGetSymbolAddress((void**)&p_pos16, g_pos16);
        cudaFuncSetAttribute((const void*)gemm_h<2,4,0>,
            cudaFuncAttributeMaxDynamicSharedMemorySize, GEMMH_SMEM);
        cudaFuncSetAttribute((const void*)gemm_h<3,4,1>,
            cudaFuncAttributeMaxDynamicSharedMemorySize, GEMMH_SMEM);
        cudaFuncSetAttribute((const void*)gemm_h<2,4,1>,
            cudaFuncAttributeMaxDynamicSharedMemorySize, GEMMH_SMEM);
        cudaFuncSetAttribute((const void*)gemm_h<0,4,1>,
            cudaFuncAttributeMaxDynamicSharedMemorySize, GEMMH_SMEM);
        cudaFuncSetAttribute((const void*)gemm_h<1,4,1>,
            cudaFuncAttributeMaxDynamicSharedMemorySize, GEMMH_SMEM);
        cudaFuncSetAttribute((const void*)gemm_h<0,16,1>,
            cudaFuncAttributeMaxDynamicSharedMemorySize, GEMMH_SMEM);
        init_done = true;
    }

    const dim3 gQKV(TOK/128, 6);
    const dim3 g256(TOK/128, 2);
    const dim3 gHID(TOK/128, 8);
    const dim3 b256(256, 1, 1);

    // ---- fused prep (no PDL attr: first kernel in chain) ----
    prep_all<<<3072 + TOK/4, 256>>>(w_in_long, w_out_long, w_in_short, w_out_short,
                                    w1, w2, pos, src, p_xqk, p_xv);

    // ---- long-range MHA ----
    // QKV long: B (wl) written by immediate predecessor prep -> PDL=0
    launch_pdl(gemm_h<2,4,0>, gQKV, b256, (size_t)GEMMH_SMEM,
               (const __half*)p_xqk, (const __half*)p_xv, (const __half*)p_wl,
               b_in_long, (const __half*)nullptr,
               (void*)p_q, (void*)p_k, (void*)p_v, 768);
    launch_pdl(attn_tc2<64>, dim3(1024*4), b256, (size_t)0,
               (const __half*)p_q, (const __half*)p_k, (const __half*)p_v,
               p_attn, 1024);
    launch_pdl(gemm_h<3,4,1>, g256, b256, (size_t)GEMMH_SMEM,
               (const __half*)p_attn, (const __half*)nullptr, (const __half*)p_wol,
               b_out_long, (const __half*)p_pos16,
               (void*)p_xqk, (void*)p_xv, (void*)nullptr, 256);

    // ---- short-range MHA ----
    launch_pdl(gemm_h<2,4,1>, gQKV, b256, (size_t)GEMMH_SMEM,
               (const __half*)p_xqk, (const __half*)p_xv, (const __half*)p_ws,
               b_in_short, (const __half*)nullptr,
               (void*)p_q, (void*)p_k, (void*)p_v, 768);
    launch_pdl(attn_tc2<128>, dim3(512*4), dim3(512, 1, 1), (size_t)0,
               (const __half*)p_q, (const __half*)p_k, (const __half*)p_v,
               p_attn, 512);
    launch_pdl(gemm_h<0,4,1>, g256, b256, (size_t)GEMMH_SMEM,
               (const __half*)p_attn, (const __half*)nullptr, (const __half*)p_wos,
               b_out_short, (const __half*)nullptr,
               (void*)p_mo16, (void*)nullptr, (void*)nullptr, 256);

    // ---- residual + LN1 ----
    launch_pdl(resid_ln1, dim3(TOK/8), b256, (size_t)0,
               src, (const __half*)p_mo16, g1, beta1, p_x16);

    // ---- FFN ----
    launch_pdl(gemm_h<1,4,1>, gHID, b256, (size_t)GEMMH_SMEM,
               (const __half*)p_x16, (const __half*)nullptr, (const __half*)p_w1,
               b1, (const __half*)nullptr,
               (void*)p_h, (void*)nullptr, (void*)nullptr, 1024);
    launch_pdl(gemm_h<0,16,1>, g256, b256, (size_t)GEMMH_SMEM,
               (const __half*)p_h, (const __half*)nullptr, (const __half*)p_w2,
               b2, (const __half*)nullptr,
               (void*)p_ff16, (void*)nullptr, (void*)nullptr, 256);

    // ---- residual + LN2 + output transpose ----
    launch_pdl(add_ln_tr, dim3(2048), b256, (size_t)0,
               (const __half*)p_x16, (const __half*)p_ff16, g2, beta2, out);
}